// round 3
// baseline (speedup 1.0000x reference)
#include <cuda_runtime.h>
#include <math.h>

#define B_  2
#define T_  2048
#define C_  2048
#define H_  16
#define D_  128
#define M_  (B_*T_)      // 4096
#define N_QKV (3*C_)     // 6144

// Scratch (device globals: allocation-free per harness rules)
__device__ float g_q[(size_t)B_*H_*T_*D_];
__device__ float g_k[(size_t)B_*H_*T_*D_];
__device__ float g_v[(size_t)B_*H_*T_*D_];
__device__ float g_attn[(size_t)M_*C_];

// ---------------------------------------------------------------------------
// SGEMM 128x128 tile, K-tile 8, 256 threads, 8x8 microtile.
// QKV=true: epilogue applies RoPE to q/k and scatters into g_q/g_k/g_v.
// QKV=false: plain store to Cout.
// ---------------------------------------------------------------------------
template<bool QKV>
__global__ void __launch_bounds__(256, 2) sgemm_kernel(
    const float* __restrict__ A, const float* __restrict__ Bm,
    float* __restrict__ Cout, int Kdim, int Ndim)
{
    __shared__ float As[8][128];
    __shared__ float Bs[8][128];

    const int tid = threadIdx.x;
    const int bm = blockIdx.y * 128;
    const int bn = blockIdx.x * 128;

    const int arow = tid >> 1;            // 0..127
    const int ak   = (tid & 1) * 4;       // 0 or 4
    const int brow = tid >> 5;            // 0..7
    const int bcol = (tid & 31) * 4;      // 0..124
    const int ty = tid >> 4;              // 0..15
    const int tx = tid & 15;              // 0..15

    float acc[8][8];
    #pragma unroll
    for (int i = 0; i < 8; i++)
        #pragma unroll
        for (int j = 0; j < 8; j++) acc[i][j] = 0.0f;

    const float* Aptr = A + (size_t)(bm + arow) * Kdim + ak;
    const float* Bptr = Bm + (size_t)brow * Ndim + bn + bcol;

    for (int k0 = 0; k0 < Kdim; k0 += 8) {
        float4 a4 = *(const float4*)(Aptr + k0);
        float4 b4 = *(const float4*)(Bptr + (size_t)k0 * Ndim);

        As[ak + 0][arow] = a4.x;
        As[ak + 1][arow] = a4.y;
        As[ak + 2][arow] = a4.z;
        As[ak + 3][arow] = a4.w;
        *(float4*)&Bs[brow][bcol] = b4;
        __syncthreads();

        #pragma unroll
        for (int kk = 0; kk < 8; kk++) {
            float a[8], b[8];
            #pragma unroll
            for (int i = 0; i < 8; i++) a[i] = As[kk][ty * 8 + i];
            #pragma unroll
            for (int j = 0; j < 8; j++) b[j] = Bs[kk][tx * 8 + j];
            #pragma unroll
            for (int i = 0; i < 8; i++)
                #pragma unroll
                for (int j = 0; j < 8; j++)
                    acc[i][j] = fmaf(a[i], b[j], acc[i][j]);
        }
        __syncthreads();
    }

    if (QKV) {
        const float LOG_BASE_OVER_D = 9.210340371976184f / (float)D_; // ln(10000)/128
        #pragma unroll
        for (int i = 0; i < 8; i++) {
            int m = bm + ty * 8 + i;
            int bidx = m >> 11;         // / T_ (2048)
            int t    = m & (T_ - 1);
            #pragma unroll
            for (int j = 0; j < 8; j += 2) {
                int n = bn + tx * 8 + j;        // even
                int sub = n / C_;               // 0=q,1=k,2=v
                int rem = n - sub * C_;
                int h = rem >> 7;               // / D_
                int d = rem & (D_ - 1);
                float v0 = acc[i][j];
                float v1 = acc[i][j + 1];
                if (sub < 2) {
                    int fi = d >> 1;
                    float inv = expf(-(float)(2 * fi) * LOG_BASE_OVER_D);
                    float s, c;
                    sincosf((float)t * inv, &s, &c);
                    float o0 = v0 * c - v1 * s;
                    float o1 = v1 * c + v0 * s;
                    v0 = o0; v1 = o1;
                }
                float* dst = (sub == 0) ? g_q : (sub == 1) ? g_k : g_v;
                size_t off = ((((size_t)bidx * H_ + h) * T_) + t) * D_ + d;
                dst[off]     = v0;
                dst[off + 1] = v1;
            }
        }
    } else {
        #pragma unroll
        for (int i = 0; i < 8; i++) {
            int m = bm + ty * 8 + i;
            float* dst = Cout + (size_t)m * Ndim + bn + tx * 8;
            float4 o0 = make_float4(acc[i][0], acc[i][1], acc[i][2], acc[i][3]);
            float4 o1 = make_float4(acc[i][4], acc[i][5], acc[i][6], acc[i][7]);
            *(float4*)(dst)     = o0;
            *(float4*)(dst + 4) = o1;
        }
    }
}

// ---------------------------------------------------------------------------
// Flash attention: 64-query tiles, 64-key blocks, online softmax, causal.
// 256 threads. Grid: (T/64, B*H).
// ---------------------------------------------------------------------------
#define QSTR 132   // padded row stride for Q/K/V tiles
#define SSTR 68    // padded row stride for S tile
#define SMEM_FLOATS (3 * 64 * QSTR + 64 * SSTR + 128)
#define SMEM_BYTES  (SMEM_FLOATS * 4)

__global__ void __launch_bounds__(256, 1) attn_kernel(float* __restrict__ out)
{
    extern __shared__ float sm[];
    float* sQ = sm;
    float* sK = sQ + 64 * QSTR;
    float* sV = sK + 64 * QSTR;
    float* sS = sV + 64 * QSTR;
    float* sAlpha = sS + 64 * SSTR;
    float* sL = sAlpha + 64;

    const int tid = threadIdx.x;
    const int qb = blockIdx.x;
    const int bh = blockIdx.y;
    const int b = bh >> 4;          // / H_
    const int h = bh & (H_ - 1);

    const float* qbase = g_q + ((size_t)bh * T_ + qb * 64) * D_;

    // Load Q tile (64 x 128)
    for (int i = tid; i < 64 * 32; i += 256) {
        int row = i >> 5, c4 = (i & 31) * 4;
        *(float4*)&sQ[row * QSTR + c4] = *(const float4*)(qbase + row * D_ + c4);
    }

    const int ty = tid >> 4;   // 0..15
    const int tx = tid & 15;   // 0..15

    float m_r = -INFINITY, l_r = 0.0f;   // valid for tid < 64 (row = tid)
    float O[4][8];
    #pragma unroll
    for (int i = 0; i < 4; i++)
        #pragma unroll
        for (int j = 0; j < 8; j++) O[i][j] = 0.0f;

    const float scale = 0.08838834764831845f;  // 1/sqrt(128)

    for (int kb = 0; kb <= qb; kb++) {
        __syncthreads();  // previous PV reads done before overwriting K/V
        const float* kbase = g_k + ((size_t)bh * T_ + kb * 64) * D_;
        const float* vbase = g_v + ((size_t)bh * T_ + kb * 64) * D_;
        for (int i = tid; i < 64 * 32; i += 256) {
            int row = i >> 5, c4 = (i & 31) * 4;
            *(float4*)&sK[row * QSTR + c4] = *(const float4*)(kbase + row * D_ + c4);
            *(float4*)&sV[row * QSTR + c4] = *(const float4*)(vbase + row * D_ + c4);
        }
        __syncthreads();

        // S = scale * Q K^T   (rows r = ty+16i, cols c = tx+16j)
        float acc[4][4];
        #pragma unroll
        for (int i = 0; i < 4; i++)
            #pragma unroll
            for (int j = 0; j < 4; j++) acc[i][j] = 0.0f;

        #pragma unroll 2
        for (int kk = 0; kk < 128; kk += 4) {
            float4 a4[4], b4[4];
            #pragma unroll
            for (int i = 0; i < 4; i++)
                a4[i] = *(const float4*)&sQ[(ty + 16 * i) * QSTR + kk];
            #pragma unroll
            for (int j = 0; j < 4; j++)
                b4[j] = *(const float4*)&sK[(tx + 16 * j) * QSTR + kk];
            #pragma unroll
            for (int i = 0; i < 4; i++)
                #pragma unroll
                for (int j = 0; j < 4; j++) {
                    acc[i][j] = fmaf(a4[i].x, b4[j].x, acc[i][j]);
                    acc[i][j] = fmaf(a4[i].y, b4[j].y, acc[i][j]);
                    acc[i][j] = fmaf(a4[i].z, b4[j].z, acc[i][j]);
                    acc[i][j] = fmaf(a4[i].w, b4[j].w, acc[i][j]);
                }
        }

        const bool diag = (kb == qb);
        #pragma unroll
        for (int i = 0; i < 4; i++)
            #pragma unroll
            for (int j = 0; j < 4; j++) {
                int r = ty + 16 * i, c = tx + 16 * j;
                float sval = acc[i][j] * scale;
                if (diag && c > r) sval = -1e30f;
                sS[r * SSTR + c] = sval;
            }
        __syncthreads();

        // Online softmax: one thread per row
        if (tid < 64) {
            int r = tid;
            float mx = -1e30f;
            for (int c = 0; c < 64; c++) mx = fmaxf(mx, sS[r * SSTR + c]);
            float nm = fmaxf(m_r, mx);
            float alpha = expf(m_r - nm);
            float sum = 0.0f;
            for (int c = 0; c < 64; c++) {
                float p = expf(sS[r * SSTR + c] - nm);
                sS[r * SSTR + c] = p;
                sum += p;
            }
            l_r = l_r * alpha + sum;
            m_r = nm;
            sAlpha[r] = alpha;
        }
        __syncthreads();

        // O = O*alpha + P @ V   (rows = ty+16i, dims = tx*8 .. +7)
        #pragma unroll
        for (int i = 0; i < 4; i++) {
            float al = sAlpha[ty + 16 * i];
            #pragma unroll
            for (int j = 0; j < 8; j++) O[i][j] *= al;
        }
        #pragma unroll 2
        for (int kk = 0; kk < 64; kk += 4) {
            float4 p4[4];
            #pragma unroll
            for (int i = 0; i < 4; i++)
                p4[i] = *(const float4*)&sS[(ty + 16 * i) * SSTR + kk];
            #pragma unroll
            for (int q = 0; q < 4; q++) {
                float4 v0 = *(const float4*)&sV[(kk + q) * QSTR + tx * 8];
                float4 v1 = *(const float4*)&sV[(kk + q) * QSTR + tx * 8 + 4];
                #pragma unroll
                for (int i = 0; i < 4; i++) {
                    float p = (q == 0) ? p4[i].x : (q == 1) ? p4[i].y
                            : (q == 2) ? p4[i].z : p4[i].w;
                    O[i][0] = fmaf(p, v0.x, O[i][0]);
                    O[i][1] = fmaf(p, v0.y, O[i][1]);
                    O[i][2] = fmaf(p, v0.z, O[i][2]);
                    O[i][3] = fmaf(p, v0.w, O[i][3]);
                    O[i][4] = fmaf(p, v1.x, O[i][4]);
                    O[i][5] = fmaf(p, v1.y, O[i][5]);
                    O[i][6] = fmaf(p, v1.z, O[i][6]);
                    O[i][7] = fmaf(p, v1.w, O[i][7]);
                }
            }
        }
    }

    if (tid < 64) sL[tid] = l_r;
    __syncthreads();

    #pragma unroll
    for (int i = 0; i < 4; i++) {
        int r = ty + 16 * i;
        float inv_l = 1.0f / sL[r];
        int t = qb * 64 + r;
        float* dst = out + ((size_t)b * T_ + t) * C_ + h * D_ + tx * 8;
        float4 o0 = make_float4(O[i][0] * inv_l, O[i][1] * inv_l,
                                O[i][2] * inv_l, O[i][3] * inv_l);
        float4 o1 = make_float4(O[i][4] * inv_l, O[i][5] * inv_l,
                                O[i][6] * inv_l, O[i][7] * inv_l);
        *(float4*)(dst)     = o0;
        *(float4*)(dst + 4) = o1;
    }
}

// ---------------------------------------------------------------------------
extern "C" void kernel_launch(void* const* d_in, const int* in_sizes, int n_in,
                              void* d_out, int out_size)
{
    const float* x     = (const float*)d_in[0];
    const float* W_qkv = (const float*)d_in[1];
    const float* W_out = (const float*)d_in[2];
    float* out = (float*)d_out;

    cudaFuncSetAttribute(attn_kernel,
                         cudaFuncAttributeMaxDynamicSharedMemorySize, SMEM_BYTES);

    // device pointers to globals (for the out-proj A operand)
    float* attn_ptr = nullptr;
    cudaGetSymbolAddress((void**)&attn_ptr, g_attn);

    // 1) QKV projection + RoPE + scatter
    {
        dim3 grid(N_QKV / 128, M_ / 128);  // (48, 32)
        sgemm_kernel<true><<<grid, 256>>>(x, W_qkv, nullptr, C_, N_QKV);
    }
    // 2) Causal flash attention -> g_attn [B,T,C]
    {
        dim3 grid(T_ / 64, B_ * H_);       // (32, 32)
        attn_kernel<<<grid, 256, SMEM_BYTES>>>(attn_ptr);
    }
    // 3) Output projection -> d_out
    {
        dim3 grid(C_ / 128, M_ / 128);     // (16, 32)
        sgemm_kernel<false><<<grid, 256>>>(attn_ptr, W_out, out, C_, C_);
    }
}

// round 5
// speedup vs baseline: 1.7269x; 1.7269x over previous
#include <cuda_runtime.h>
#include <cuda_bf16.h>
#include <math.h>
#include <stdint.h>

#define B_  2
#define T_  2048
#define C_  2048
#define H_  16
#define D_  128
#define M_  (B_*T_)      // 4096
#define N_QKV (3*C_)     // 6144

// ---------------------------------------------------------------------------
// Device scratch (allocation-free per harness rules)
// ---------------------------------------------------------------------------
__device__ float g_q[(size_t)B_*H_*T_*D_];
__device__ float g_k[(size_t)B_*H_*T_*D_];
__device__ float g_v[(size_t)B_*H_*T_*D_];
__device__ float g_attn[(size_t)M_*C_];

__device__ __nv_bfloat16 g_hiA[(size_t)M_*C_];
__device__ __nv_bfloat16 g_loA[(size_t)M_*C_];
__device__ __nv_bfloat16 g_hiB1[(size_t)N_QKV*C_];
__device__ __nv_bfloat16 g_loB1[(size_t)N_QKV*C_];
__device__ __nv_bfloat16 g_hiB2[(size_t)C_*C_];
__device__ __nv_bfloat16 g_loB2[(size_t)C_*C_];

// ---------------------------------------------------------------------------
// Warp-level bf16 MMA (sm_80+ PTX; no sm_103a-gated features)
// ---------------------------------------------------------------------------
__device__ __forceinline__ void mma16816(float* c, const uint32_t* a, const uint32_t* b) {
    asm volatile(
        "mma.sync.aligned.m16n8k16.row.col.f32.bf16.bf16.f32 "
        "{%0,%1,%2,%3}, {%4,%5,%6,%7}, {%8,%9}, {%0,%1,%2,%3};"
        : "+f"(c[0]), "+f"(c[1]), "+f"(c[2]), "+f"(c[3])
        : "r"(a[0]), "r"(a[1]), "r"(a[2]), "r"(a[3]), "r"(b[0]), "r"(b[1]));
}

// ---------------------------------------------------------------------------
// Conversion kernels: fp32 -> (hi, lo) bf16 split
// ---------------------------------------------------------------------------
__global__ void split_kernel(const float* __restrict__ src,
                             __nv_bfloat16* __restrict__ hi,
                             __nv_bfloat16* __restrict__ lo, int n4)
{
    int i = blockIdx.x * blockDim.x + threadIdx.x;
    if (i >= n4) return;
    float4 v = ((const float4*)src)[i];
    __nv_bfloat16 h0 = __float2bfloat16(v.x);
    __nv_bfloat16 h1 = __float2bfloat16(v.y);
    __nv_bfloat16 h2 = __float2bfloat16(v.z);
    __nv_bfloat16 h3 = __float2bfloat16(v.w);
    __nv_bfloat16 l0 = __float2bfloat16(v.x - __bfloat162float(h0));
    __nv_bfloat16 l1 = __float2bfloat16(v.y - __bfloat162float(h1));
    __nv_bfloat16 l2 = __float2bfloat16(v.z - __bfloat162float(h2));
    __nv_bfloat16 l3 = __float2bfloat16(v.w - __bfloat162float(h3));
    __nv_bfloat162* hp = (__nv_bfloat162*)hi;
    __nv_bfloat162* lp = (__nv_bfloat162*)lo;
    hp[i*2]   = __nv_bfloat162{h0, h1};
    hp[i*2+1] = __nv_bfloat162{h2, h3};
    lp[i*2]   = __nv_bfloat162{l0, l1};
    lp[i*2+1] = __nv_bfloat162{l2, l3};
}

// Transpose + split: W [K=2048, N] -> hi/lo [N, 2048]
__global__ void tsplit_kernel(const float* __restrict__ W,
                              __nv_bfloat16* __restrict__ hi,
                              __nv_bfloat16* __restrict__ lo, int N)
{
    __shared__ float t[32][33];
    int n0 = blockIdx.x * 32, k0 = blockIdx.y * 32;
    int tx = threadIdx.x, ty = threadIdx.y;   // (32, 8)
    #pragma unroll
    for (int i = 0; i < 4; i++)
        t[ty + i*8][tx] = W[(size_t)(k0 + ty + i*8) * N + n0 + tx];
    __syncthreads();
    #pragma unroll
    for (int i = 0; i < 4; i++) {
        int r = ty + i*8;
        float v = t[tx][r];
        __nv_bfloat16 h = __float2bfloat16(v);
        __nv_bfloat16 l = __float2bfloat16(v - __bfloat162float(h));
        size_t o = (size_t)(n0 + r) * 2048 + k0 + tx;
        hi[o] = h;
        lo[o] = l;
    }
}

// ---------------------------------------------------------------------------
// HMMA split-bf16 GEMM: C[M,N] = A[M,2048] * B[N,2048]^T  (fp32 via 3 MMAs)
// CTA 128x128, 256 threads (8 warps as 4m x 2n, warp tile 32x64),
// K-chunk 32, double-buffered dynamic smem (80 KB), padded stride 40.
// EPI=1: RoPE + scatter to g_q/g_k/g_v.  EPI=0: plain store to Cout.
// ---------------------------------------------------------------------------
#define ASTR 40                       // padded bf16 row stride in smem
#define BUF_ELEMS (4 * 128 * ASTR)    // 20480 bf16 per buffer
#define SMEM_GEMM (2 * BUF_ELEMS * 2) // 81920 bytes

template<int EPI>
__global__ void __launch_bounds__(256, 1) hmma_gemm(
    const __nv_bfloat16* __restrict__ hiA, const __nv_bfloat16* __restrict__ loA,
    const __nv_bfloat16* __restrict__ hiB, const __nv_bfloat16* __restrict__ loB,
    float* __restrict__ Cout, int Ntot)
{
    extern __shared__ char smraw[];
    __nv_bfloat16* sm = (__nv_bfloat16*)smraw;

    const int tid = threadIdx.x;
    const int lane = tid & 31;
    const int wid = tid >> 5;
    const int warp_m = wid & 3;       // 0..3 -> 32 rows each
    const int warp_n = wid >> 2;      // 0..1 -> 64 cols each
    const int bn = blockIdx.x * 128;
    const int bm = blockIdx.y * 128;

    const int row0 = tid >> 2;        // 0..63
    const int row1 = row0 + 64;       // 64..127
    const int slot = (tid & 3) * 8;   // k-elem offset {0,8,16,24}

    float acc[2][8][4];
    #pragma unroll
    for (int mt = 0; mt < 2; mt++)
        #pragma unroll
        for (int nt = 0; nt < 8; nt++)
            #pragma unroll
            for (int q = 0; q < 4; q++) acc[mt][nt][q] = 0.0f;

    uint4 rAh[2], rAl[2], rBh[2], rBl[2];

    auto LDG = [&](int k0) {
        rAh[0] = *(const uint4*)(hiA + (size_t)(bm + row0) * 2048 + k0 + slot);
        rAh[1] = *(const uint4*)(hiA + (size_t)(bm + row1) * 2048 + k0 + slot);
        rAl[0] = *(const uint4*)(loA + (size_t)(bm + row0) * 2048 + k0 + slot);
        rAl[1] = *(const uint4*)(loA + (size_t)(bm + row1) * 2048 + k0 + slot);
        rBh[0] = *(const uint4*)(hiB + (size_t)(bn + row0) * 2048 + k0 + slot);
        rBh[1] = *(const uint4*)(hiB + (size_t)(bn + row1) * 2048 + k0 + slot);
        rBl[0] = *(const uint4*)(loB + (size_t)(bn + row0) * 2048 + k0 + slot);
        rBl[1] = *(const uint4*)(loB + (size_t)(bn + row1) * 2048 + k0 + slot);
    };
    auto STS = [&](int buf) {
        __nv_bfloat16* s = sm + buf * BUF_ELEMS;
        *(uint4*)(s +     0 + row0 * ASTR + slot) = rAh[0];
        *(uint4*)(s +     0 + row1 * ASTR + slot) = rAh[1];
        *(uint4*)(s +  5120 + row0 * ASTR + slot) = rAl[0];
        *(uint4*)(s +  5120 + row1 * ASTR + slot) = rAl[1];
        *(uint4*)(s + 10240 + row0 * ASTR + slot) = rBh[0];
        *(uint4*)(s + 10240 + row1 * ASTR + slot) = rBh[1];
        *(uint4*)(s + 15360 + row0 * ASTR + slot) = rBl[0];
        *(uint4*)(s + 15360 + row1 * ASTR + slot) = rBl[1];
    };

    const int lr = lane >> 2;          // fragment row / n
    const int lk = (lane & 3) * 2;     // fragment k pair

    auto COMPUTE = [&](int buf) {
        const __nv_bfloat16* s = sm + buf * BUF_ELEMS;
        const __nv_bfloat16* sAh = s;
        const __nv_bfloat16* sAl = s + 5120;
        const __nv_bfloat16* sBh = s + 10240;
        const __nv_bfloat16* sBl = s + 15360;
        #pragma unroll
        for (int ks = 0; ks < 32; ks += 16) {
            uint32_t ah[2][4], al[2][4], bh[8][2], bl[8][2];
            #pragma unroll
            for (int mt = 0; mt < 2; mt++) {
                int base = (warp_m * 32 + mt * 16 + lr) * ASTR + ks + lk;
                ah[mt][0] = *(const uint32_t*)(sAh + base);
                ah[mt][1] = *(const uint32_t*)(sAh + base + 8 * ASTR);
                ah[mt][2] = *(const uint32_t*)(sAh + base + 8);
                ah[mt][3] = *(const uint32_t*)(sAh + base + 8 * ASTR + 8);
                al[mt][0] = *(const uint32_t*)(sAl + base);
                al[mt][1] = *(const uint32_t*)(sAl + base + 8 * ASTR);
                al[mt][2] = *(const uint32_t*)(sAl + base + 8);
                al[mt][3] = *(const uint32_t*)(sAl + base + 8 * ASTR + 8);
            }
            #pragma unroll
            for (int nt = 0; nt < 8; nt++) {
                int base = (warp_n * 64 + nt * 8 + lr) * ASTR + ks + lk;
                bh[nt][0] = *(const uint32_t*)(sBh + base);
                bh[nt][1] = *(const uint32_t*)(sBh + base + 8);
                bl[nt][0] = *(const uint32_t*)(sBl + base);
                bl[nt][1] = *(const uint32_t*)(sBl + base + 8);
            }
            #pragma unroll
            for (int mt = 0; mt < 2; mt++)
                #pragma unroll
                for (int nt = 0; nt < 8; nt++) {
                    mma16816(acc[mt][nt], ah[mt], bh[nt]);
                    mma16816(acc[mt][nt], ah[mt], bl[nt]);
                    mma16816(acc[mt][nt], al[mt], bh[nt]);
                }
        }
    };

    // main loop: K = 2048 in 64 chunks of 32, double-buffered
    LDG(0);
    STS(0);
    __syncthreads();
    for (int c = 0; c < 64; c++) {
        const int b = c & 1;
        if (c + 1 < 64) LDG((c + 1) * 32);
        COMPUTE(b);
        if (c + 1 < 64) STS(b ^ 1);
        __syncthreads();
    }

    // ---- Epilogue ----
    if (EPI == 1) {
        const int sub = bn >> 11;              // 0=q, 1=k, 2=v (CTA-constant)
        const int h   = (bn >> 7) & (H_ - 1);
        float* base_ptr = (sub == 0) ? g_q : (sub == 1) ? g_k : g_v;
        const float ROPE_K = 9.210340371976184f / (float)D_;   // ln(10000)/128
        float invf[8];
        #pragma unroll
        for (int nt = 0; nt < 8; nt++) {
            int d = warp_n * 64 + nt * 8 + lk;
            invf[nt] = expf(-(float)d * ROPE_K);
        }
        #pragma unroll
        for (int mt = 0; mt < 2; mt++) {
            #pragma unroll
            for (int half = 0; half < 2; half++) {
                int m = bm + warp_m * 32 + mt * 16 + lr + half * 8;
                int bidx = m >> 11;
                int t    = m & (T_ - 1);
                float* dst = base_ptr + (((size_t)(bidx * H_ + h)) * T_ + t) * (size_t)D_;
                #pragma unroll
                for (int nt = 0; nt < 8; nt++) {
                    int d = warp_n * 64 + nt * 8 + lk;
                    float v0 = acc[mt][nt][half * 2 + 0];
                    float v1 = acc[mt][nt][half * 2 + 1];
                    if (sub < 2) {
                        float sn, cs;
                        sincosf((float)t * invf[nt], &sn, &cs);
                        float o0 = v0 * cs - v1 * sn;
                        float o1 = v1 * cs + v0 * sn;
                        v0 = o0; v1 = o1;
                    }
                    *(float2*)(dst + d) = make_float2(v0, v1);
                }
            }
        }
    } else {
        #pragma unroll
        for (int mt = 0; mt < 2; mt++) {
            #pragma unroll
            for (int half = 0; half < 2; half++) {
                int m = bm + warp_m * 32 + mt * 16 + lr + half * 8;
                float* dst = Cout + (size_t)m * Ntot + bn + warp_n * 64 + lk;
                #pragma unroll
                for (int nt = 0; nt < 8; nt++)
                    *(float2*)(dst + nt * 8) =
                        make_float2(acc[mt][nt][half * 2 + 0], acc[mt][nt][half * 2 + 1]);
            }
        }
    }
}

// ---------------------------------------------------------------------------
// Flash attention (fp32, unchanged from R3): 64-query tiles, online softmax.
// ---------------------------------------------------------------------------
#define QSTR 132
#define SSTR 68
#define SMEM_FLOATS (3 * 64 * QSTR + 64 * SSTR + 128)
#define SMEM_BYTES  (SMEM_FLOATS * 4)

__global__ void __launch_bounds__(256, 1) attn_kernel(float* __restrict__ out)
{
    extern __shared__ float sm[];
    float* sQ = sm;
    float* sK = sQ + 64 * QSTR;
    float* sV = sK + 64 * QSTR;
    float* sS = sV + 64 * QSTR;
    float* sAlpha = sS + 64 * SSTR;
    float* sL = sAlpha + 64;

    const int tid = threadIdx.x;
    const int qb = blockIdx.x;
    const int bh = blockIdx.y;
    const int b = bh >> 4;
    const int h = bh & (H_ - 1);

    const float* qbase = g_q + ((size_t)bh * T_ + qb * 64) * D_;

    for (int i = tid; i < 64 * 32; i += 256) {
        int row = i >> 5, c4 = (i & 31) * 4;
        *(float4*)&sQ[row * QSTR + c4] = *(const float4*)(qbase + row * D_ + c4);
    }

    const int ty = tid >> 4;
    const int tx = tid & 15;

    float m_r = -INFINITY, l_r = 0.0f;
    float O[4][8];
    #pragma unroll
    for (int i = 0; i < 4; i++)
        #pragma unroll
        for (int j = 0; j < 8; j++) O[i][j] = 0.0f;

    const float scale = 0.08838834764831845f;

    for (int kb = 0; kb <= qb; kb++) {
        __syncthreads();
        const float* kbase = g_k + ((size_t)bh * T_ + kb * 64) * D_;
        const float* vbase = g_v + ((size_t)bh * T_ + kb * 64) * D_;
        for (int i = tid; i < 64 * 32; i += 256) {
            int row = i >> 5, c4 = (i & 31) * 4;
            *(float4*)&sK[row * QSTR + c4] = *(const float4*)(kbase + row * D_ + c4);
            *(float4*)&sV[row * QSTR + c4] = *(const float4*)(vbase + row * D_ + c4);
        }
        __syncthreads();

        float acc[4][4];
        #pragma unroll
        for (int i = 0; i < 4; i++)
            #pragma unroll
            for (int j = 0; j < 4; j++) acc[i][j] = 0.0f;

        #pragma unroll 2
        for (int kk = 0; kk < 128; kk += 4) {
            float4 a4[4], b4[4];
            #pragma unroll
            for (int i = 0; i < 4; i++)
                a4[i] = *(const float4*)&sQ[(ty + 16 * i) * QSTR + kk];
            #pragma unroll
            for (int j = 0; j < 4; j++)
                b4[j] = *(const float4*)&sK[(tx + 16 * j) * QSTR + kk];
            #pragma unroll
            for (int i = 0; i < 4; i++)
                #pragma unroll
                for (int j = 0; j < 4; j++) {
                    acc[i][j] = fmaf(a4[i].x, b4[j].x, acc[i][j]);
                    acc[i][j] = fmaf(a4[i].y, b4[j].y, acc[i][j]);
                    acc[i][j] = fmaf(a4[i].z, b4[j].z, acc[i][j]);
                    acc[i][j] = fmaf(a4[i].w, b4[j].w, acc[i][j]);
                }
        }

        const bool diag = (kb == qb);
        #pragma unroll
        for (int i = 0; i < 4; i++)
            #pragma unroll
            for (int j = 0; j < 4; j++) {
                int r = ty + 16 * i, c = tx + 16 * j;
                float sval = acc[i][j] * scale;
                if (diag && c > r) sval = -1e30f;
                sS[r * SSTR + c] = sval;
            }
        __syncthreads();

        if (tid < 64) {
            int r = tid;
            float mx = -1e30f;
            for (int c = 0; c < 64; c++) mx = fmaxf(mx, sS[r * SSTR + c]);
            float nm = fmaxf(m_r, mx);
            float alpha = expf(m_r - nm);
            float sum = 0.0f;
            for (int c = 0; c < 64; c++) {
                float p = expf(sS[r * SSTR + c] - nm);
                sS[r * SSTR + c] = p;
                sum += p;
            }
            l_r = l_r * alpha + sum;
            m_r = nm;
            sAlpha[r] = alpha;
        }
        __syncthreads();

        #pragma unroll
        for (int i = 0; i < 4; i++) {
            float al = sAlpha[ty + 16 * i];
            #pragma unroll
            for (int j = 0; j < 8; j++) O[i][j] *= al;
        }
        #pragma unroll 2
        for (int kk = 0; kk < 64; kk += 4) {
            float4 p4[4];
            #pragma unroll
            for (int i = 0; i < 4; i++)
                p4[i] = *(const float4*)&sS[(ty + 16 * i) * SSTR + kk];
            #pragma unroll
            for (int q = 0; q < 4; q++) {
                float4 v0 = *(const float4*)&sV[(kk + q) * QSTR + tx * 8];
                float4 v1 = *(const float4*)&sV[(kk + q) * QSTR + tx * 8 + 4];
                #pragma unroll
                for (int i = 0; i < 4; i++) {
                    float p = (q == 0) ? p4[i].x : (q == 1) ? p4[i].y
                            : (q == 2) ? p4[i].z : p4[i].w;
                    O[i][0] = fmaf(p, v0.x, O[i][0]);
                    O[i][1] = fmaf(p, v0.y, O[i][1]);
                    O[i][2] = fmaf(p, v0.z, O[i][2]);
                    O[i][3] = fmaf(p, v0.w, O[i][3]);
                    O[i][4] = fmaf(p, v1.x, O[i][4]);
                    O[i][5] = fmaf(p, v1.y, O[i][5]);
                    O[i][6] = fmaf(p, v1.z, O[i][6]);
                    O[i][7] = fmaf(p, v1.w, O[i][7]);
                }
            }
        }
    }

    if (tid < 64) sL[tid] = l_r;
    __syncthreads();

    #pragma unroll
    for (int i = 0; i < 4; i++) {
        int r = ty + 16 * i;
        float inv_l = 1.0f / sL[r];
        int t = qb * 64 + r;
        float* dst = out + ((size_t)b * T_ + t) * C_ + h * D_ + tx * 8;
        *(float4*)(dst) = make_float4(O[i][0] * inv_l, O[i][1] * inv_l,
                                      O[i][2] * inv_l, O[i][3] * inv_l);
        *(float4*)(dst + 4) = make_float4(O[i][4] * inv_l, O[i][5] * inv_l,
                                          O[i][6] * inv_l, O[i][7] * inv_l);
    }
}

// ---------------------------------------------------------------------------
extern "C" void kernel_launch(void* const* d_in, const int* in_sizes, int n_in,
                              void* d_out, int out_size)
{
    const float* x     = (const float*)d_in[0];
    const float* W_qkv = (const float*)d_in[1];
    const float* W_out = (const float*)d_in[2];
    float* out = (float*)d_out;

    cudaFuncSetAttribute(attn_kernel,
                         cudaFuncAttributeMaxDynamicSharedMemorySize, SMEM_BYTES);
    cudaFuncSetAttribute(hmma_gemm<1>,
                         cudaFuncAttributeMaxDynamicSharedMemorySize, SMEM_GEMM);
    cudaFuncSetAttribute(hmma_gemm<0>,
                         cudaFuncAttributeMaxDynamicSharedMemorySize, SMEM_GEMM);

    float* attn_ptr = nullptr;
    __nv_bfloat16 *hiA, *loA, *hiB1, *loB1, *hiB2, *loB2;
    cudaGetSymbolAddress((void**)&attn_ptr, g_attn);
    cudaGetSymbolAddress((void**)&hiA,  g_hiA);
    cudaGetSymbolAddress((void**)&loA,  g_loA);
    cudaGetSymbolAddress((void**)&hiB1, g_hiB1);
    cudaGetSymbolAddress((void**)&loB1, g_loB1);
    cudaGetSymbolAddress((void**)&hiB2, g_hiB2);
    cudaGetSymbolAddress((void**)&loB2, g_loB2);

    const int n4 = (M_ * C_) / 4;

    // 1) split x -> hi/lo bf16
    split_kernel<<<(n4 + 255) / 256, 256>>>(x, hiA, loA, n4);
    // 2) transpose+split W_qkv [2048, 6144] -> [6144, 2048]
    tsplit_kernel<<<dim3(N_QKV / 32, C_ / 32), dim3(32, 8)>>>(W_qkv, hiB1, loB1, N_QKV);
    // 3) QKV projection (HMMA tensor cores) + RoPE + scatter
    hmma_gemm<1><<<dim3(N_QKV / 128, M_ / 128), 256, SMEM_GEMM>>>(
        hiA, loA, hiB1, loB1, nullptr, N_QKV);
    // 4) causal flash attention -> g_attn
    attn_kernel<<<dim3(T_ / 64, B_ * H_), 256, SMEM_BYTES>>>(attn_ptr);
    // 5) split attention output
    split_kernel<<<(n4 + 255) / 256, 256>>>(attn_ptr, hiA, loA, n4);
    // 6) transpose+split W_out [2048, 2048]
    tsplit_kernel<<<dim3(C_ / 32, C_ / 32), dim3(32, 8)>>>(W_out, hiB2, loB2, C_);
    // 7) output projection (HMMA tensor cores) -> d_out
    hmma_gemm<0><<<dim3(C_ / 128, M_ / 128), 256, SMEM_GEMM>>>(
        hiA, loA, hiB2, loB2, out, C_);
}

// round 9
// speedup vs baseline: 2.6430x; 1.5305x over previous
#include <cuda_runtime.h>
#include <cuda_bf16.h>
#include <math.h>
#include <stdint.h>

#define B_  2
#define T_  2048
#define C_  2048
#define H_  16
#define D_  128
#define M_  (B_*T_)      // 4096
#define N_QKV (3*C_)     // 6144

// ---------------------------------------------------------------------------
// Device scratch (allocation-free per harness rules)
// ---------------------------------------------------------------------------
__device__ __nv_bfloat16 g_qh[(size_t)B_*H_*T_*D_];
__device__ __nv_bfloat16 g_ql[(size_t)B_*H_*T_*D_];
__device__ __nv_bfloat16 g_kh[(size_t)B_*H_*T_*D_];
__device__ __nv_bfloat16 g_kl[(size_t)B_*H_*T_*D_];
__device__ __nv_bfloat16 g_vth[(size_t)B_*H_*D_*T_];   // transposed [B,H,D,T]
__device__ __nv_bfloat16 g_vtl[(size_t)B_*H_*D_*T_];

__device__ __nv_bfloat16 g_hiA[(size_t)M_*C_];
__device__ __nv_bfloat16 g_loA[(size_t)M_*C_];
__device__ __nv_bfloat16 g_hiB1[(size_t)N_QKV*C_];
__device__ __nv_bfloat16 g_loB1[(size_t)N_QKV*C_];
__device__ __nv_bfloat16 g_hiB2[(size_t)C_*C_];
__device__ __nv_bfloat16 g_loB2[(size_t)C_*C_];

// ---------------------------------------------------------------------------
// PTX helpers
// ---------------------------------------------------------------------------
__device__ __forceinline__ void mma16816(float* c, const uint32_t* a, const uint32_t* b) {
    asm volatile(
        "mma.sync.aligned.m16n8k16.row.col.f32.bf16.bf16.f32 "
        "{%0,%1,%2,%3}, {%4,%5,%6,%7}, {%8,%9}, {%0,%1,%2,%3};"
        : "+f"(c[0]), "+f"(c[1]), "+f"(c[2]), "+f"(c[3])
        : "r"(a[0]), "r"(a[1]), "r"(a[2]), "r"(a[3]), "r"(b[0]), "r"(b[1]));
}

__device__ __forceinline__ uint32_t smem_to_u32(const void* p) {
    uint32_t a;
    asm("{ .reg .u64 t; cvta.to.shared.u64 t, %1; cvt.u32.u64 %0, t; }" : "=r"(a) : "l"(p));
    return a;
}

__device__ __forceinline__ void cp16(uint32_t dst, const void* src) {
    asm volatile("cp.async.cg.shared.global [%0], [%1], 16;" :: "r"(dst), "l"(src));
}
#define CP_COMMIT() asm volatile("cp.async.commit_group;" ::: "memory")
#define CP_WAIT0()  asm volatile("cp.async.wait_group 0;" ::: "memory")

// pack two fp32 -> bf16x2 (lo = first arg -> lower half)
__device__ __forceinline__ uint32_t packbf(float lo, float hi) {
    uint32_t r;
    asm("cvt.rn.bf16x2.f32 %0, %1, %2;" : "=r"(r) : "f"(hi), "f"(lo));
    return r;
}

// ---------------------------------------------------------------------------
// fp32 -> (hi, lo) bf16 split conversions
// ---------------------------------------------------------------------------
__global__ void split_kernel(const float* __restrict__ src,
                             __nv_bfloat16* __restrict__ hi,
                             __nv_bfloat16* __restrict__ lo, int n4)
{
    int i = blockIdx.x * blockDim.x + threadIdx.x;
    if (i >= n4) return;
    float4 v = ((const float4*)src)[i];
    __nv_bfloat16 h0 = __float2bfloat16(v.x);
    __nv_bfloat16 h1 = __float2bfloat16(v.y);
    __nv_bfloat16 h2 = __float2bfloat16(v.z);
    __nv_bfloat16 h3 = __float2bfloat16(v.w);
    __nv_bfloat16 l0 = __float2bfloat16(v.x - __bfloat162float(h0));
    __nv_bfloat16 l1 = __float2bfloat16(v.y - __bfloat162float(h1));
    __nv_bfloat16 l2 = __float2bfloat16(v.z - __bfloat162float(h2));
    __nv_bfloat16 l3 = __float2bfloat16(v.w - __bfloat162float(h3));
    __nv_bfloat162* hp = (__nv_bfloat162*)hi;
    __nv_bfloat162* lp = (__nv_bfloat162*)lo;
    hp[i*2]   = __nv_bfloat162{h0, h1};
    hp[i*2+1] = __nv_bfloat162{h2, h3};
    lp[i*2]   = __nv_bfloat162{l0, l1};
    lp[i*2+1] = __nv_bfloat162{l2, l3};
}

__global__ void tsplit_kernel(const float* __restrict__ W,
                              __nv_bfloat16* __restrict__ hi,
                              __nv_bfloat16* __restrict__ lo, int N)
{
    __shared__ float t[32][33];
    int n0 = blockIdx.x * 32, k0 = blockIdx.y * 32;
    int tx = threadIdx.x, ty = threadIdx.y;
    #pragma unroll
    for (int i = 0; i < 4; i++)
        t[ty + i*8][tx] = W[(size_t)(k0 + ty + i*8) * N + n0 + tx];
    __syncthreads();
    #pragma unroll
    for (int i = 0; i < 4; i++) {
        int r = ty + i*8;
        float v = t[tx][r];
        __nv_bfloat16 h = __float2bfloat16(v);
        __nv_bfloat16 l = __float2bfloat16(v - __bfloat162float(h));
        size_t o = (size_t)(n0 + r) * 2048 + k0 + tx;
        hi[o] = h;
        lo[o] = l;
    }
}

// ---------------------------------------------------------------------------
// HMMA split-bf16 GEMM. EPI=1: RoPE + bf16 hi/lo scatter (Q,K normal;
// V transposed). EPI=0: plain fp32 store.
// ---------------------------------------------------------------------------
#define ASTR 40
#define BUF_ELEMS (4 * 128 * ASTR)
#define SMEM_GEMM (2 * BUF_ELEMS * 2)

template<int EPI>
__global__ void __launch_bounds__(256, 1) hmma_gemm(
    const __nv_bfloat16* __restrict__ hiA, const __nv_bfloat16* __restrict__ loA,
    const __nv_bfloat16* __restrict__ hiB, const __nv_bfloat16* __restrict__ loB,
    float* __restrict__ Cout, int Ntot)
{
    extern __shared__ char smraw[];
    __nv_bfloat16* sm = (__nv_bfloat16*)smraw;

    const int tid = threadIdx.x;
    const int lane = tid & 31;
    const int wid = tid >> 5;
    const int warp_m = wid & 3;
    const int warp_n = wid >> 2;
    const int bn = blockIdx.x * 128;
    const int bm = blockIdx.y * 128;

    const int row0 = tid >> 2;
    const int row1 = row0 + 64;
    const int slot = (tid & 3) * 8;

    float acc[2][8][4];
    #pragma unroll
    for (int mt = 0; mt < 2; mt++)
        #pragma unroll
        for (int nt = 0; nt < 8; nt++)
            #pragma unroll
            for (int q = 0; q < 4; q++) acc[mt][nt][q] = 0.0f;

    uint4 rAh[2], rAl[2], rBh[2], rBl[2];

    auto LDG = [&](int k0) {
        rAh[0] = *(const uint4*)(hiA + (size_t)(bm + row0) * 2048 + k0 + slot);
        rAh[1] = *(const uint4*)(hiA + (size_t)(bm + row1) * 2048 + k0 + slot);
        rAl[0] = *(const uint4*)(loA + (size_t)(bm + row0) * 2048 + k0 + slot);
        rAl[1] = *(const uint4*)(loA + (size_t)(bm + row1) * 2048 + k0 + slot);
        rBh[0] = *(const uint4*)(hiB + (size_t)(bn + row0) * 2048 + k0 + slot);
        rBh[1] = *(const uint4*)(hiB + (size_t)(bn + row1) * 2048 + k0 + slot);
        rBl[0] = *(const uint4*)(loB + (size_t)(bn + row0) * 2048 + k0 + slot);
        rBl[1] = *(const uint4*)(loB + (size_t)(bn + row1) * 2048 + k0 + slot);
    };
    auto STS = [&](int buf) {
        __nv_bfloat16* s = sm + buf * BUF_ELEMS;
        *(uint4*)(s +     0 + row0 * ASTR + slot) = rAh[0];
        *(uint4*)(s +     0 + row1 * ASTR + slot) = rAh[1];
        *(uint4*)(s +  5120 + row0 * ASTR + slot) = rAl[0];
        *(uint4*)(s +  5120 + row1 * ASTR + slot) = rAl[1];
        *(uint4*)(s + 10240 + row0 * ASTR + slot) = rBh[0];
        *(uint4*)(s + 10240 + row1 * ASTR + slot) = rBh[1];
        *(uint4*)(s + 15360 + row0 * ASTR + slot) = rBl[0];
        *(uint4*)(s + 15360 + row1 * ASTR + slot) = rBl[1];
    };

    const int lr = lane >> 2;
    const int lk = (lane & 3) * 2;

    auto COMPUTE = [&](int buf) {
        const __nv_bfloat16* s = sm + buf * BUF_ELEMS;
        const __nv_bfloat16* sAh = s;
        const __nv_bfloat16* sAl = s + 5120;
        const __nv_bfloat16* sBh = s + 10240;
        const __nv_bfloat16* sBl = s + 15360;
        #pragma unroll
        for (int ks = 0; ks < 32; ks += 16) {
            uint32_t ah[2][4], al[2][4], bh[8][2], bl[8][2];
            #pragma unroll
            for (int mt = 0; mt < 2; mt++) {
                int base = (warp_m * 32 + mt * 16 + lr) * ASTR + ks + lk;
                ah[mt][0] = *(const uint32_t*)(sAh + base);
                ah[mt][1] = *(const uint32_t*)(sAh + base + 8 * ASTR);
                ah[mt][2] = *(const uint32_t*)(sAh + base + 8);
                ah[mt][3] = *(const uint32_t*)(sAh + base + 8 * ASTR + 8);
                al[mt][0] = *(const uint32_t*)(sAl + base);
                al[mt][1] = *(const uint32_t*)(sAl + base + 8 * ASTR);
                al[mt][2] = *(const uint32_t*)(sAl + base + 8);
                al[mt][3] = *(const uint32_t*)(sAl + base + 8 * ASTR + 8);
            }
            #pragma unroll
            for (int nt = 0; nt < 8; nt++) {
                int base = (warp_n * 64 + nt * 8 + lr) * ASTR + ks + lk;
                bh[nt][0] = *(const uint32_t*)(sBh + base);
                bh[nt][1] = *(const uint32_t*)(sBh + base + 8);
                bl[nt][0] = *(const uint32_t*)(sBl + base);
                bl[nt][1] = *(const uint32_t*)(sBl + base + 8);
            }
            #pragma unroll
            for (int mt = 0; mt < 2; mt++)
                #pragma unroll
                for (int nt = 0; nt < 8; nt++) {
                    mma16816(acc[mt][nt], ah[mt], bh[nt]);
                    mma16816(acc[mt][nt], ah[mt], bl[nt]);
                    mma16816(acc[mt][nt], al[mt], bh[nt]);
                }
        }
    };

    LDG(0);
    STS(0);
    __syncthreads();
    for (int c = 0; c < 64; c++) {
        const int b = c & 1;
        if (c + 1 < 64) LDG((c + 1) * 32);
        COMPUTE(b);
        if (c + 1 < 64) STS(b ^ 1);
        __syncthreads();
    }

    if (EPI == 1) {
        const int sub = bn >> 11;              // 0=q, 1=k, 2=v
        const int h   = (bn >> 7) & (H_ - 1);
        const float ROPE_K = 9.210340371976184f / (float)D_;
        float invf[8];
        #pragma unroll
        for (int nt = 0; nt < 8; nt++)
            invf[nt] = expf(-(float)(warp_n * 64 + nt * 8 + lk) * ROPE_K);
        #pragma unroll
        for (int mt = 0; mt < 2; mt++) {
            #pragma unroll
            for (int half = 0; half < 2; half++) {
                int m = bm + warp_m * 32 + mt * 16 + lr + half * 8;
                int bidx = m >> 11;
                int t    = m & (T_ - 1);
                size_t rowoff = ((size_t)(bidx * H_ + h) * T_ + t) * D_;
                #pragma unroll
                for (int nt = 0; nt < 8; nt++) {
                    int d = warp_n * 64 + nt * 8 + lk;
                    float v0 = acc[mt][nt][half * 2 + 0];
                    float v1 = acc[mt][nt][half * 2 + 1];
                    if (sub < 2) {
                        float sn, cs;
                        sincosf((float)t * invf[nt], &sn, &cs);
                        float o0 = v0 * cs - v1 * sn;
                        float o1 = v1 * cs + v0 * sn;
                        v0 = o0; v1 = o1;
                    }
                    __nv_bfloat16 h0 = __float2bfloat16(v0);
                    __nv_bfloat16 h1 = __float2bfloat16(v1);
                    __nv_bfloat16 l0 = __float2bfloat16(v0 - __bfloat162float(h0));
                    __nv_bfloat16 l1 = __float2bfloat16(v1 - __bfloat162float(h1));
                    if (sub < 2) {
                        __nv_bfloat16* dh = (sub == 0) ? g_qh : g_kh;
                        __nv_bfloat16* dl = (sub == 0) ? g_ql : g_kl;
                        *(__nv_bfloat162*)(dh + rowoff + d) = __nv_bfloat162{h0, h1};
                        *(__nv_bfloat162*)(dl + rowoff + d) = __nv_bfloat162{l0, l1};
                    } else {
                        size_t vb = ((size_t)(bidx * H_ + h) * D_ + d) * T_ + t;
                        g_vth[vb]      = h0;
                        g_vth[vb + T_] = h1;
                        g_vtl[vb]      = l0;
                        g_vtl[vb + T_] = l1;
                    }
                }
            }
        }
    } else {
        #pragma unroll
        for (int mt = 0; mt < 2; mt++) {
            #pragma unroll
            for (int half = 0; half < 2; half++) {
                int m = bm + warp_m * 32 + mt * 16 + lr + half * 8;
                float* dst = Cout + (size_t)m * Ntot + bn + warp_n * 64 + lk;
                #pragma unroll
                for (int nt = 0; nt < 8; nt++)
                    *(float2*)(dst + nt * 8) =
                        make_float2(acc[mt][nt][half * 2 + 0], acc[mt][nt][half * 2 + 1]);
            }
        }
    }
}

// ---------------------------------------------------------------------------
// HMMA flash attention.
// CTA: 128 queries, 8 warps (16 rows each). Key blocks of 64, cp.async
// double-buffered. Split-bf16 for QK^T and PV. Output -> g_hiA/g_loA.
// ---------------------------------------------------------------------------
#define SQ_H   0
#define SQ_L   34816
#define SBUF0  69632
#define KB_H   0
#define KB_L   17408
#define VB_H   34816
#define VB_L   53248
#define ABUF_SZ 71680
#define SMEM_ATTN (SBUF0 + 2 * ABUF_SZ)   // 212992 bytes

__global__ void __launch_bounds__(256, 1) attn_hmma(
    __nv_bfloat16* __restrict__ outh, __nv_bfloat16* __restrict__ outl)
{
    extern __shared__ char sm[];
    const uint32_t sb = smem_to_u32(sm);

    const int tid  = threadIdx.x;
    const int lane = tid & 31;
    const int w    = tid >> 5;
    const int lr   = lane >> 2;
    const int q    = lane & 3;
    const int qt   = 15 - blockIdx.x;          // longest tiles first
    const int bh   = blockIdx.y;
    const int b    = bh >> 4;
    const int h    = bh & (H_ - 1);

    const size_t bhT = (size_t)bh * T_;

    // ---- load Q tile (128 x 128, hi/lo) via cp.async ----
    {
        const __nv_bfloat16* qh = g_qh + (bhT + qt * 128) * D_;
        const __nv_bfloat16* ql = g_ql + (bhT + qt * 128) * D_;
        #pragma unroll
        for (int i = 0; i < 8; i++) {
            int idx = tid + i * 256;
            int row = idx >> 4, c = idx & 15;
            cp16(sb + SQ_H + row * 272 + c * 16, qh + row * D_ + c * 8);
            cp16(sb + SQ_L + row * 272 + c * 16, ql + row * D_ + c * 8);
        }
    }

    auto loadKV = [&](int blk, int buf) {
        uint32_t bo = sb + SBUF0 + buf * ABUF_SZ;
        const __nv_bfloat16* kh = g_kh + (bhT + blk * 64) * D_;
        const __nv_bfloat16* kl = g_kl + (bhT + blk * 64) * D_;
        const __nv_bfloat16* vh = g_vth + (size_t)bh * D_ * T_ + blk * 64;
        const __nv_bfloat16* vl = g_vtl + (size_t)bh * D_ * T_ + blk * 64;
        #pragma unroll
        for (int i = 0; i < 4; i++) {
            int idx = tid + i * 256;
            int row = idx >> 4, c = idx & 15;            // K: 64 rows x 16 chunks
            cp16(bo + KB_H + row * 272 + c * 16, kh + row * D_ + c * 8);
            cp16(bo + KB_L + row * 272 + c * 16, kl + row * D_ + c * 8);
            int vr = idx >> 3, vc = idx & 7;             // V: 128 rows x 8 chunks
            cp16(bo + VB_H + vr * 144 + vc * 16, vh + (size_t)vr * T_ + vc * 8);
            cp16(bo + VB_L + vr * 144 + vc * 16, vl + (size_t)vr * T_ + vc * 8);
        }
    };

    loadKV(0, 0);
    CP_COMMIT();
    CP_WAIT0();
    __syncthreads();

    const int nblk = 2 * qt + 2;
    const float scale = 0.08838834764831845f;   // 1/sqrt(128)

    float mr0 = -INFINITY, mr1 = -INFINITY, lw0 = 0.0f, lw1 = 0.0f;
    float O[16][4];
    #pragma unroll
    for (int n = 0; n < 16; n++)
        #pragma unroll
        for (int e = 0; e < 4; e++) O[n][e] = 0.0f;

    const int rbase = qt * 128 + 16 * w;        // global row of lr==0

    for (int blk = 0; blk < nblk; blk++) {
        const uint32_t bo = sb + SBUF0 + (blk & 1) * ABUF_SZ;
        if (blk + 1 < nblk) {
            loadKV(blk + 1, (blk & 1) ^ 1);
            CP_COMMIT();
        }

        // ---- S = Q K^T (split bf16, 16x64 per warp) ----
        float s[8][4];
        #pragma unroll
        for (int n = 0; n < 8; n++)
            #pragma unroll
            for (int e = 0; e < 4; e++) s[n][e] = 0.0f;

        #pragma unroll
        for (int kt = 0; kt < 8; kt++) {
            uint32_t ah[4], al[4];
            uint32_t ab = sb + SQ_H + (16 * w + lr) * 272 + kt * 32 + 4 * q;
            ah[0] = *(const uint32_t*)(sm + (ab - sb));
            ah[1] = *(const uint32_t*)(sm + (ab - sb) + 8 * 272);
            ah[2] = *(const uint32_t*)(sm + (ab - sb) + 16);
            ah[3] = *(const uint32_t*)(sm + (ab - sb) + 8 * 272 + 16);
            uint32_t lb = (ab - sb) + (SQ_L - SQ_H);
            al[0] = *(const uint32_t*)(sm + lb);
            al[1] = *(const uint32_t*)(sm + lb + 8 * 272);
            al[2] = *(const uint32_t*)(sm + lb + 16);
            al[3] = *(const uint32_t*)(sm + lb + 8 * 272 + 16);
            #pragma unroll
            for (int nt = 0; nt < 8; nt++) {
                uint32_t bbo = (bo - sb) + KB_H + (nt * 8 + lr) * 272 + kt * 32 + 4 * q;
                uint32_t bhf[2], blf[2];
                bhf[0] = *(const uint32_t*)(sm + bbo);
                bhf[1] = *(const uint32_t*)(sm + bbo + 16);
                blf[0] = *(const uint32_t*)(sm + bbo + (KB_L - KB_H));
                blf[1] = *(const uint32_t*)(sm + bbo + (KB_L - KB_H) + 16);
                mma16816(s[nt], ah, bhf);
                mma16816(s[nt], ah, blf);
                mma16816(s[nt], al, bhf);
            }
        }

        // ---- scale + causal mask ----
        // Mask needed iff the block's last key exceeds the warp's MIN row.
        const bool need_mask = (blk * 64 + 63) > rbase;
        #pragma unroll
        for (int nt = 0; nt < 8; nt++) {
            #pragma unroll
            for (int e = 0; e < 4; e++) {
                float v = s[nt][e] * scale;
                if (need_mask) {
                    int ckey = blk * 64 + nt * 8 + 2 * q + (e & 1);
                    int r = rbase + lr + ((e >> 1) ? 8 : 0);
                    if (ckey > r) v = -1e30f;
                }
                s[nt][e] = v;
            }
        }

        // ---- online softmax (intra-quad shuffles) ----
        float mx0 = -1e30f, mx1 = -1e30f;
        #pragma unroll
        for (int nt = 0; nt < 8; nt++) {
            mx0 = fmaxf(mx0, fmaxf(s[nt][0], s[nt][1]));
            mx1 = fmaxf(mx1, fmaxf(s[nt][2], s[nt][3]));
        }
        mx0 = fmaxf(mx0, __shfl_xor_sync(0xffffffff, mx0, 1));
        mx0 = fmaxf(mx0, __shfl_xor_sync(0xffffffff, mx0, 2));
        mx1 = fmaxf(mx1, __shfl_xor_sync(0xffffffff, mx1, 1));
        mx1 = fmaxf(mx1, __shfl_xor_sync(0xffffffff, mx1, 2));
        float mn0 = fmaxf(mr0, mx0);
        float mn1 = fmaxf(mr1, mx1);
        float alpha0 = __expf(mr0 - mn0);
        float alpha1 = __expf(mr1 - mn1);

        float sum0 = 0.0f, sum1 = 0.0f;
        uint32_t aPh[4][4], aPl[4][4];
        #pragma unroll
        for (int nt = 0; nt < 8; nt++) {
            float p0 = __expf(s[nt][0] - mn0);
            float p1 = __expf(s[nt][1] - mn0);
            float p2 = __expf(s[nt][2] - mn1);
            float p3 = __expf(s[nt][3] - mn1);
            sum0 += p0 + p1;
            sum1 += p2 + p3;
            float h0 = __bfloat162float(__float2bfloat16(p0));
            float h1 = __bfloat162float(__float2bfloat16(p1));
            float h2 = __bfloat162float(__float2bfloat16(p2));
            float h3 = __bfloat162float(__float2bfloat16(p3));
            int kt2 = nt >> 1;
            int hi2 = (nt & 1) << 1;
            aPh[kt2][hi2 + 0] = packbf(h0, h1);
            aPh[kt2][hi2 + 1] = packbf(h2, h3);
            aPl[kt2][hi2 + 0] = packbf(p0 - h0, p1 - h1);
            aPl[kt2][hi2 + 1] = packbf(p2 - h2, p3 - h3);
        }
        sum0 += __shfl_xor_sync(0xffffffff, sum0, 1);
        sum0 += __shfl_xor_sync(0xffffffff, sum0, 2);
        sum1 += __shfl_xor_sync(0xffffffff, sum1, 1);
        sum1 += __shfl_xor_sync(0xffffffff, sum1, 2);
        lw0 = lw0 * alpha0 + sum0;
        lw1 = lw1 * alpha1 + sum1;
        mr0 = mn0;
        mr1 = mn1;

        // ---- O = O*alpha + P V (split bf16) ----
        #pragma unroll
        for (int n = 0; n < 16; n++) {
            O[n][0] *= alpha0; O[n][1] *= alpha0;
            O[n][2] *= alpha1; O[n][3] *= alpha1;
        }
        #pragma unroll
        for (int kt2 = 0; kt2 < 4; kt2++) {
            #pragma unroll
            for (int nt2 = 0; nt2 < 16; nt2++) {
                uint32_t vbo = (bo - sb) + VB_H + (nt2 * 8 + lr) * 144 + kt2 * 32 + 4 * q;
                uint32_t bhf[2], blf[2];
                bhf[0] = *(const uint32_t*)(sm + vbo);
                bhf[1] = *(const uint32_t*)(sm + vbo + 16);
                blf[0] = *(const uint32_t*)(sm + vbo + (VB_L - VB_H));
                blf[1] = *(const uint32_t*)(sm + vbo + (VB_L - VB_H) + 16);
                mma16816(O[nt2], aPh[kt2], bhf);
                mma16816(O[nt2], aPh[kt2], blf);
                mma16816(O[nt2], aPl[kt2], bhf);
            }
        }

        if (blk + 1 < nblk) {
            CP_WAIT0();
            __syncthreads();
        }
    }

    // ---- epilogue: normalize, split to bf16 hi/lo, store to out-proj A ----
    const float inv0 = 1.0f / lw0;
    const float inv1 = 1.0f / lw1;
    const int m0 = b * T_ + rbase + lr;
    const int m1 = m0 + 8;
    #pragma unroll
    for (int nt2 = 0; nt2 < 16; nt2++) {
        int col = h * D_ + nt2 * 8 + 2 * q;
        float o0 = O[nt2][0] * inv0, o1 = O[nt2][1] * inv0;
        float o2 = O[nt2][2] * inv1, o3 = O[nt2][3] * inv1;
        __nv_bfloat16 h0 = __float2bfloat16(o0), h1 = __float2bfloat16(o1);
        __nv_bfloat16 h2 = __float2bfloat16(o2), h3 = __float2bfloat16(o3);
        __nv_bfloat16 l0 = __float2bfloat16(o0 - __bfloat162float(h0));
        __nv_bfloat16 l1 = __float2bfloat16(o1 - __bfloat162float(h1));
        __nv_bfloat16 l2 = __float2bfloat16(o2 - __bfloat162float(h2));
        __nv_bfloat16 l3 = __float2bfloat16(o3 - __bfloat162float(h3));
        *(__nv_bfloat162*)(outh + (size_t)m0 * C_ + col) = __nv_bfloat162{h0, h1};
        *(__nv_bfloat162*)(outl + (size_t)m0 * C_ + col) = __nv_bfloat162{l0, l1};
        *(__nv_bfloat162*)(outh + (size_t)m1 * C_ + col) = __nv_bfloat162{h2, h3};
        *(__nv_bfloat162*)(outl + (size_t)m1 * C_ + col) = __nv_bfloat162{l2, l3};
    }
}

// ---------------------------------------------------------------------------
extern "C" void kernel_launch(void* const* d_in, const int* in_sizes, int n_in,
                              void* d_out, int out_size)
{
    const float* x     = (const float*)d_in[0];
    const float* W_qkv = (const float*)d_in[1];
    const float* W_out = (const float*)d_in[2];
    float* out = (float*)d_out;

    cudaFuncSetAttribute(attn_hmma,
                         cudaFuncAttributeMaxDynamicSharedMemorySize, SMEM_ATTN);
    cudaFuncSetAttribute(hmma_gemm<1>,
                         cudaFuncAttributeMaxDynamicSharedMemorySize, SMEM_GEMM);
    cudaFuncSetAttribute(hmma_gemm<0>,
                         cudaFuncAttributeMaxDynamicSharedMemorySize, SMEM_GEMM);

    __nv_bfloat16 *hiA, *loA, *hiB1, *loB1, *hiB2, *loB2;
    cudaGetSymbolAddress((void**)&hiA,  g_hiA);
    cudaGetSymbolAddress((void**)&loA,  g_loA);
    cudaGetSymbolAddress((void**)&hiB1, g_hiB1);
    cudaGetSymbolAddress((void**)&loB1, g_loB1);
    cudaGetSymbolAddress((void**)&hiB2, g_hiB2);
    cudaGetSymbolAddress((void**)&loB2, g_loB2);

    const int n4 = (M_ * C_) / 4;

    // 1) split x -> hi/lo bf16 (A operand of QKV GEMM)
    split_kernel<<<(n4 + 255) / 256, 256>>>(x, hiA, loA, n4);
    // 2) transpose+split weights
    tsplit_kernel<<<dim3(N_QKV / 32, C_ / 32), dim3(32, 8)>>>(W_qkv, hiB1, loB1, N_QKV);
    tsplit_kernel<<<dim3(C_ / 32, C_ / 32), dim3(32, 8)>>>(W_out, hiB2, loB2, C_);
    // 3) QKV projection + RoPE -> bf16 hi/lo q/k (and transposed v)
    hmma_gemm<1><<<dim3(N_QKV / 128, M_ / 128), 256, SMEM_GEMM>>>(
        hiA, loA, hiB1, loB1, nullptr, N_QKV);
    // 4) HMMA flash attention -> g_hiA/g_loA (A operand of out-proj)
    attn_hmma<<<dim3(T_ / 128, B_ * H_), 256, SMEM_ATTN>>>(hiA, loA);
    // 5) output projection -> d_out
    hmma_gemm<0><<<dim3(C_ / 128, M_ / 128), 256, SMEM_GEMM>>>(
        hiA, loA, hiB2, loB2, out, C_);
}

// round 10
// speedup vs baseline: 2.9624x; 1.1208x over previous
#include <cuda_runtime.h>
#include <cuda_bf16.h>
#include <math.h>
#include <stdint.h>

#define B_  2
#define T_  2048
#define C_  2048
#define H_  16
#define D_  128
#define M_  (B_*T_)      // 4096
#define N_QKV (3*C_)     // 6144

// ---------------------------------------------------------------------------
// Device scratch (allocation-free per harness rules)
// ---------------------------------------------------------------------------
__device__ __nv_bfloat16 g_qh[(size_t)B_*H_*T_*D_];
__device__ __nv_bfloat16 g_ql[(size_t)B_*H_*T_*D_];
__device__ __nv_bfloat16 g_kh[(size_t)B_*H_*T_*D_];
__device__ __nv_bfloat16 g_kl[(size_t)B_*H_*T_*D_];
__device__ __nv_bfloat16 g_vth[(size_t)B_*H_*D_*T_];   // transposed [B,H,D,T]
__device__ __nv_bfloat16 g_vtl[(size_t)B_*H_*D_*T_];

__device__ __nv_bfloat16 g_hiA[(size_t)M_*C_];
__device__ __nv_bfloat16 g_loA[(size_t)M_*C_];
__device__ __nv_bfloat16 g_hiB1[(size_t)N_QKV*C_];
__device__ __nv_bfloat16 g_loB1[(size_t)N_QKV*C_];
__device__ __nv_bfloat16 g_hiB2[(size_t)C_*C_];
__device__ __nv_bfloat16 g_loB2[(size_t)C_*C_];

// ---------------------------------------------------------------------------
// PTX helpers
// ---------------------------------------------------------------------------
__device__ __forceinline__ void mma16816(float* c, const uint32_t* a, const uint32_t* b) {
    asm volatile(
        "mma.sync.aligned.m16n8k16.row.col.f32.bf16.bf16.f32 "
        "{%0,%1,%2,%3}, {%4,%5,%6,%7}, {%8,%9}, {%0,%1,%2,%3};"
        : "+f"(c[0]), "+f"(c[1]), "+f"(c[2]), "+f"(c[3])
        : "r"(a[0]), "r"(a[1]), "r"(a[2]), "r"(a[3]), "r"(b[0]), "r"(b[1]));
}

__device__ __forceinline__ void ldsm4(uint32_t* r, uint32_t addr) {
    asm volatile("ldmatrix.sync.aligned.m8n8.x4.shared.b16 {%0,%1,%2,%3}, [%4];"
        : "=r"(r[0]), "=r"(r[1]), "=r"(r[2]), "=r"(r[3]) : "r"(addr));
}

__device__ __forceinline__ uint32_t smem_to_u32(const void* p) {
    uint32_t a;
    asm("{ .reg .u64 t; cvta.to.shared.u64 t, %1; cvt.u32.u64 %0, t; }" : "=r"(a) : "l"(p));
    return a;
}

__device__ __forceinline__ void cp16(uint32_t dst, const void* src) {
    asm volatile("cp.async.cg.shared.global [%0], [%1], 16;" :: "r"(dst), "l"(src));
}
#define CP_COMMIT() asm volatile("cp.async.commit_group;" ::: "memory")
#define CP_WAIT0()  asm volatile("cp.async.wait_group 0;" ::: "memory")
#define CP_WAIT1()  asm volatile("cp.async.wait_group 1;" ::: "memory")

// pack two fp32 -> bf16x2 (lo = first arg -> lower half)
__device__ __forceinline__ uint32_t packbf(float lo, float hi) {
    uint32_t r;
    asm("cvt.rn.bf16x2.f32 %0, %1, %2;" : "=r"(r) : "f"(hi), "f"(lo));
    return r;
}

// ---------------------------------------------------------------------------
// fp32 -> (hi, lo) bf16 split conversions
// ---------------------------------------------------------------------------
__global__ void split_kernel(const float* __restrict__ src,
                             __nv_bfloat16* __restrict__ hi,
                             __nv_bfloat16* __restrict__ lo, int n4)
{
    int i = blockIdx.x * blockDim.x + threadIdx.x;
    if (i >= n4) return;
    float4 v = ((const float4*)src)[i];
    __nv_bfloat16 h0 = __float2bfloat16(v.x);
    __nv_bfloat16 h1 = __float2bfloat16(v.y);
    __nv_bfloat16 h2 = __float2bfloat16(v.z);
    __nv_bfloat16 h3 = __float2bfloat16(v.w);
    __nv_bfloat16 l0 = __float2bfloat16(v.x - __bfloat162float(h0));
    __nv_bfloat16 l1 = __float2bfloat16(v.y - __bfloat162float(h1));
    __nv_bfloat16 l2 = __float2bfloat16(v.z - __bfloat162float(h2));
    __nv_bfloat16 l3 = __float2bfloat16(v.w - __bfloat162float(h3));
    __nv_bfloat162* hp = (__nv_bfloat162*)hi;
    __nv_bfloat162* lp = (__nv_bfloat162*)lo;
    hp[i*2]   = __nv_bfloat162{h0, h1};
    hp[i*2+1] = __nv_bfloat162{h2, h3};
    lp[i*2]   = __nv_bfloat162{l0, l1};
    lp[i*2+1] = __nv_bfloat162{l2, l3};
}

__global__ void tsplit_kernel(const float* __restrict__ W,
                              __nv_bfloat16* __restrict__ hi,
                              __nv_bfloat16* __restrict__ lo, int N)
{
    __shared__ float t[32][33];
    int n0 = blockIdx.x * 32, k0 = blockIdx.y * 32;
    int tx = threadIdx.x, ty = threadIdx.y;
    #pragma unroll
    for (int i = 0; i < 4; i++)
        t[ty + i*8][tx] = W[(size_t)(k0 + ty + i*8) * N + n0 + tx];
    __syncthreads();
    #pragma unroll
    for (int i = 0; i < 4; i++) {
        int r = ty + i*8;
        float v = t[tx][r];
        __nv_bfloat16 h = __float2bfloat16(v);
        __nv_bfloat16 l = __float2bfloat16(v - __bfloat162float(h));
        size_t o = (size_t)(n0 + r) * 2048 + k0 + tx;
        hi[o] = h;
        lo[o] = l;
    }
}

// ---------------------------------------------------------------------------
// HMMA split-bf16 GEMM, cp.async 3-stage pipeline + ldmatrix fragments.
// CTA 128x128, 8 warps (4m x 2n). K-chunk 32.
// EPI=1: RoPE + bf16 hi/lo scatter (Q,K normal; V transposed).
// EPI=0: plain fp32 store.
// ---------------------------------------------------------------------------
#define ASTR 40                          // padded bf16 row stride
#define TILE_ELEMS (128 * ASTR)          // 5120 elems per matrix tile
#define TILE_B     (TILE_ELEMS * 2)      // 10240 bytes
#define STAGE_B    (4 * TILE_B)          // 40960 bytes per stage
#define NSTAGE     3
#define SMEM_GEMM  (NSTAGE * STAGE_B)    // 122880 bytes
#define NCH        64                    // 2048 / 32

template<int EPI>
__global__ void __launch_bounds__(256, 1) hmma_gemm(
    const __nv_bfloat16* __restrict__ hiA, const __nv_bfloat16* __restrict__ loA,
    const __nv_bfloat16* __restrict__ hiB, const __nv_bfloat16* __restrict__ loB,
    float* __restrict__ Cout, int Ntot)
{
    extern __shared__ char smraw[];
    const uint32_t sb = smem_to_u32(smraw);

    const int tid = threadIdx.x;
    const int lane = tid & 31;
    const int wid = tid >> 5;
    const int warp_m = wid & 3;
    const int warp_n = wid >> 2;
    const int bn = blockIdx.x * 128;
    const int bm = blockIdx.y * 128;

    float acc[2][8][4];
    #pragma unroll
    for (int mt = 0; mt < 2; mt++)
        #pragma unroll
        for (int nt = 0; nt < 8; nt++)
            #pragma unroll
            for (int e = 0; e < 4; e++) acc[mt][nt][e] = 0.0f;

    // cp.async stage loader: 4 matrices x 128 rows x 32 bf16 (4 x 16B per row)
    const int lrow = tid >> 2;                  // 0..63
    const int lc   = (tid & 3) * 8;             // elem offset {0,8,16,24}
    auto load_stage = [&](int st, int k0) {
        uint32_t bo = sb + st * STAGE_B;
        #pragma unroll
        for (int i = 0; i < 2; i++) {
            int row = lrow + i * 64;
            uint32_t so = (uint32_t)(row * ASTR + lc) * 2;
            size_t ga = (size_t)(bm + row) * 2048 + k0 + lc;
            size_t gb = (size_t)(bn + row) * 2048 + k0 + lc;
            cp16(bo + 0*TILE_B + so, hiA + ga);
            cp16(bo + 1*TILE_B + so, loA + ga);
            cp16(bo + 2*TILE_B + so, hiB + gb);
            cp16(bo + 3*TILE_B + so, loB + gb);
        }
    };

    // ldmatrix address components
    const int a_row = warp_m * 32 + (lane & 7) + ((lane >> 3) & 1) * 8;
    const int a_k8  = (lane >> 4) * 8;
    const int b_row = warp_n * 64 + (lane & 7) + (lane >> 4) * 8;
    const int b_k8  = ((lane >> 3) & 1) * 8;

    auto compute_stage = [&](int st) {
        uint32_t bo = sb + st * STAGE_B;
        #pragma unroll
        for (int ks = 0; ks < 32; ks += 16) {
            uint32_t ah[2][4], al[2][4], bh[4][4], bl[4][4];
            #pragma unroll
            for (int mt = 0; mt < 2; mt++) {
                uint32_t ao = (uint32_t)((a_row + mt * 16) * ASTR + ks + a_k8) * 2;
                ldsm4(ah[mt], bo + 0*TILE_B + ao);
                ldsm4(al[mt], bo + 1*TILE_B + ao);
            }
            #pragma unroll
            for (int p = 0; p < 4; p++) {
                uint32_t bo2 = (uint32_t)((b_row + p * 16) * ASTR + ks + b_k8) * 2;
                ldsm4(bh[p], bo + 2*TILE_B + bo2);
                ldsm4(bl[p], bo + 3*TILE_B + bo2);
            }
            #pragma unroll
            for (int mt = 0; mt < 2; mt++)
                #pragma unroll
                for (int p = 0; p < 4; p++) {
                    mma16816(acc[mt][2*p+0], ah[mt], &bh[p][0]);
                    mma16816(acc[mt][2*p+0], ah[mt], &bl[p][0]);
                    mma16816(acc[mt][2*p+0], al[mt], &bh[p][0]);
                    mma16816(acc[mt][2*p+1], ah[mt], &bh[p][2]);
                    mma16816(acc[mt][2*p+1], ah[mt], &bl[p][2]);
                    mma16816(acc[mt][2*p+1], al[mt], &bh[p][2]);
                }
        }
    };

    // prime pipeline: stages 0, 1
    load_stage(0, 0);
    CP_COMMIT();
    load_stage(1, 32);
    CP_COMMIT();

    for (int c = 0; c < NCH; c++) {
        CP_WAIT1();
        __syncthreads();
        compute_stage(c % NSTAGE);
        if (c + 2 < NCH)
            load_stage((c + 2) % NSTAGE, (c + 2) * 32);
        CP_COMMIT();
    }

    // ---- Epilogue ----
    const int lr = lane >> 2;
    const int lk = (lane & 3) * 2;

    if (EPI == 1) {
        const int sub = bn >> 11;              // 0=q, 1=k, 2=v
        const int h   = (bn >> 7) & (H_ - 1);
        const float ROPE_K = 9.210340371976184f / (float)D_;
        float invf[8];
        #pragma unroll
        for (int nt = 0; nt < 8; nt++)
            invf[nt] = expf(-(float)(warp_n * 64 + nt * 8 + lk) * ROPE_K);
        #pragma unroll
        for (int mt = 0; mt < 2; mt++) {
            #pragma unroll
            for (int half = 0; half < 2; half++) {
                int m = bm + warp_m * 32 + mt * 16 + lr + half * 8;
                int bidx = m >> 11;
                int t    = m & (T_ - 1);
                size_t rowoff = ((size_t)(bidx * H_ + h) * T_ + t) * D_;
                #pragma unroll
                for (int nt = 0; nt < 8; nt++) {
                    int d = warp_n * 64 + nt * 8 + lk;
                    float v0 = acc[mt][nt][half * 2 + 0];
                    float v1 = acc[mt][nt][half * 2 + 1];
                    if (sub < 2) {
                        float sn, cs;
                        sincosf((float)t * invf[nt], &sn, &cs);
                        float o0 = v0 * cs - v1 * sn;
                        float o1 = v1 * cs + v0 * sn;
                        v0 = o0; v1 = o1;
                    }
                    __nv_bfloat16 h0 = __float2bfloat16(v0);
                    __nv_bfloat16 h1 = __float2bfloat16(v1);
                    __nv_bfloat16 l0 = __float2bfloat16(v0 - __bfloat162float(h0));
                    __nv_bfloat16 l1 = __float2bfloat16(v1 - __bfloat162float(h1));
                    if (sub < 2) {
                        __nv_bfloat16* dh = (sub == 0) ? g_qh : g_kh;
                        __nv_bfloat16* dl = (sub == 0) ? g_ql : g_kl;
                        *(__nv_bfloat162*)(dh + rowoff + d) = __nv_bfloat162{h0, h1};
                        *(__nv_bfloat162*)(dl + rowoff + d) = __nv_bfloat162{l0, l1};
                    } else {
                        size_t vb = ((size_t)(bidx * H_ + h) * D_ + d) * T_ + t;
                        g_vth[vb]      = h0;
                        g_vth[vb + T_] = h1;
                        g_vtl[vb]      = l0;
                        g_vtl[vb + T_] = l1;
                    }
                }
            }
        }
    } else {
        #pragma unroll
        for (int mt = 0; mt < 2; mt++) {
            #pragma unroll
            for (int half = 0; half < 2; half++) {
                int m = bm + warp_m * 32 + mt * 16 + lr + half * 8;
                float* dst = Cout + (size_t)m * Ntot + bn + warp_n * 64 + lk;
                #pragma unroll
                for (int nt = 0; nt < 8; nt++)
                    *(float2*)(dst + nt * 8) =
                        make_float2(acc[mt][nt][half * 2 + 0], acc[mt][nt][half * 2 + 1]);
            }
        }
    }
}

// ---------------------------------------------------------------------------
// HMMA flash attention (unchanged from R9).
// ---------------------------------------------------------------------------
#define SQ_H   0
#define SQ_L   34816
#define SBUF0  69632
#define KB_H   0
#define KB_L   17408
#define VB_H   34816
#define VB_L   53248
#define ABUF_SZ 71680
#define SMEM_ATTN (SBUF0 + 2 * ABUF_SZ)   // 212992 bytes

__global__ void __launch_bounds__(256, 1) attn_hmma(
    __nv_bfloat16* __restrict__ outh, __nv_bfloat16* __restrict__ outl)
{
    extern __shared__ char sm[];
    const uint32_t sb = smem_to_u32(sm);

    const int tid  = threadIdx.x;
    const int lane = tid & 31;
    const int w    = tid >> 5;
    const int lr   = lane >> 2;
    const int q    = lane & 3;
    const int qt   = 15 - blockIdx.x;          // longest tiles first
    const int bh   = blockIdx.y;
    const int b    = bh >> 4;
    const int h    = bh & (H_ - 1);

    const size_t bhT = (size_t)bh * T_;

    {
        const __nv_bfloat16* qh = g_qh + (bhT + qt * 128) * D_;
        const __nv_bfloat16* ql = g_ql + (bhT + qt * 128) * D_;
        #pragma unroll
        for (int i = 0; i < 8; i++) {
            int idx = tid + i * 256;
            int row = idx >> 4, c = idx & 15;
            cp16(sb + SQ_H + row * 272 + c * 16, qh + row * D_ + c * 8);
            cp16(sb + SQ_L + row * 272 + c * 16, ql + row * D_ + c * 8);
        }
    }

    auto loadKV = [&](int blk, int buf) {
        uint32_t bo = sb + SBUF0 + buf * ABUF_SZ;
        const __nv_bfloat16* kh = g_kh + (bhT + blk * 64) * D_;
        const __nv_bfloat16* kl = g_kl + (bhT + blk * 64) * D_;
        const __nv_bfloat16* vh = g_vth + (size_t)bh * D_ * T_ + blk * 64;
        const __nv_bfloat16* vl = g_vtl + (size_t)bh * D_ * T_ + blk * 64;
        #pragma unroll
        for (int i = 0; i < 4; i++) {
            int idx = tid + i * 256;
            int row = idx >> 4, c = idx & 15;
            cp16(bo + KB_H + row * 272 + c * 16, kh + row * D_ + c * 8);
            cp16(bo + KB_L + row * 272 + c * 16, kl + row * D_ + c * 8);
            int vr = idx >> 3, vc = idx & 7;
            cp16(bo + VB_H + vr * 144 + vc * 16, vh + (size_t)vr * T_ + vc * 8);
            cp16(bo + VB_L + vr * 144 + vc * 16, vl + (size_t)vr * T_ + vc * 8);
        }
    };

    loadKV(0, 0);
    CP_COMMIT();
    CP_WAIT0();
    __syncthreads();

    const int nblk = 2 * qt + 2;
    const float scale = 0.08838834764831845f;

    float mr0 = -INFINITY, mr1 = -INFINITY, lw0 = 0.0f, lw1 = 0.0f;
    float O[16][4];
    #pragma unroll
    for (int n = 0; n < 16; n++)
        #pragma unroll
        for (int e = 0; e < 4; e++) O[n][e] = 0.0f;

    const int rbase = qt * 128 + 16 * w;

    for (int blk = 0; blk < nblk; blk++) {
        const uint32_t bo = sb + SBUF0 + (blk & 1) * ABUF_SZ;
        if (blk + 1 < nblk) {
            loadKV(blk + 1, (blk & 1) ^ 1);
            CP_COMMIT();
        }

        float s[8][4];
        #pragma unroll
        for (int n = 0; n < 8; n++)
            #pragma unroll
            for (int e = 0; e < 4; e++) s[n][e] = 0.0f;

        #pragma unroll
        for (int kt = 0; kt < 8; kt++) {
            uint32_t ah[4], al[4];
            uint32_t ab = sb + SQ_H + (16 * w + lr) * 272 + kt * 32 + 4 * q;
            ah[0] = *(const uint32_t*)(sm + (ab - sb));
            ah[1] = *(const uint32_t*)(sm + (ab - sb) + 8 * 272);
            ah[2] = *(const uint32_t*)(sm + (ab - sb) + 16);
            ah[3] = *(const uint32_t*)(sm + (ab - sb) + 8 * 272 + 16);
            uint32_t lb = (ab - sb) + (SQ_L - SQ_H);
            al[0] = *(const uint32_t*)(sm + lb);
            al[1] = *(const uint32_t*)(sm + lb + 8 * 272);
            al[2] = *(const uint32_t*)(sm + lb + 16);
            al[3] = *(const uint32_t*)(sm + lb + 8 * 272 + 16);
            #pragma unroll
            for (int nt = 0; nt < 8; nt++) {
                uint32_t bbo = (bo - sb) + KB_H + (nt * 8 + lr) * 272 + kt * 32 + 4 * q;
                uint32_t bhf[2], blf[2];
                bhf[0] = *(const uint32_t*)(sm + bbo);
                bhf[1] = *(const uint32_t*)(sm + bbo + 16);
                blf[0] = *(const uint32_t*)(sm + bbo + (KB_L - KB_H));
                blf[1] = *(const uint32_t*)(sm + bbo + (KB_L - KB_H) + 16);
                mma16816(s[nt], ah, bhf);
                mma16816(s[nt], ah, blf);
                mma16816(s[nt], al, bhf);
            }
        }

        const bool need_mask = (blk * 64 + 63) > rbase;
        #pragma unroll
        for (int nt = 0; nt < 8; nt++) {
            #pragma unroll
            for (int e = 0; e < 4; e++) {
                float v = s[nt][e] * scale;
                if (need_mask) {
                    int ckey = blk * 64 + nt * 8 + 2 * q + (e & 1);
                    int r = rbase + lr + ((e >> 1) ? 8 : 0);
                    if (ckey > r) v = -1e30f;
                }
                s[nt][e] = v;
            }
        }

        float mx0 = -1e30f, mx1 = -1e30f;
        #pragma unroll
        for (int nt = 0; nt < 8; nt++) {
            mx0 = fmaxf(mx0, fmaxf(s[nt][0], s[nt][1]));
            mx1 = fmaxf(mx1, fmaxf(s[nt][2], s[nt][3]));
        }
        mx0 = fmaxf(mx0, __shfl_xor_sync(0xffffffff, mx0, 1));
        mx0 = fmaxf(mx0, __shfl_xor_sync(0xffffffff, mx0, 2));
        mx1 = fmaxf(mx1, __shfl_xor_sync(0xffffffff, mx1, 1));
        mx1 = fmaxf(mx1, __shfl_xor_sync(0xffffffff, mx1, 2));
        float mn0 = fmaxf(mr0, mx0);
        float mn1 = fmaxf(mr1, mx1);
        float alpha0 = __expf(mr0 - mn0);
        float alpha1 = __expf(mr1 - mn1);

        float sum0 = 0.0f, sum1 = 0.0f;
        uint32_t aPh[4][4], aPl[4][4];
        #pragma unroll
        for (int nt = 0; nt < 8; nt++) {
            float p0 = __expf(s[nt][0] - mn0);
            float p1 = __expf(s[nt][1] - mn0);
            float p2 = __expf(s[nt][2] - mn1);
            float p3 = __expf(s[nt][3] - mn1);
            sum0 += p0 + p1;
            sum1 += p2 + p3;
            float h0 = __bfloat162float(__float2bfloat16(p0));
            float h1 = __bfloat162float(__float2bfloat16(p1));
            float h2 = __bfloat162float(__float2bfloat16(p2));
            float h3 = __bfloat162float(__float2bfloat16(p3));
            int kt2 = nt >> 1;
            int hi2 = (nt & 1) << 1;
            aPh[kt2][hi2 + 0] = packbf(h0, h1);
            aPh[kt2][hi2 + 1] = packbf(h2, h3);
            aPl[kt2][hi2 + 0] = packbf(p0 - h0, p1 - h1);
            aPl[kt2][hi2 + 1] = packbf(p2 - h2, p3 - h3);
        }
        sum0 += __shfl_xor_sync(0xffffffff, sum0, 1);
        sum0 += __shfl_xor_sync(0xffffffff, sum0, 2);
        sum1 += __shfl_xor_sync(0xffffffff, sum1, 1);
        sum1 += __shfl_xor_sync(0xffffffff, sum1, 2);
        lw0 = lw0 * alpha0 + sum0;
        lw1 = lw1 * alpha1 + sum1;
        mr0 = mn0;
        mr1 = mn1;

        #pragma unroll
        for (int n = 0; n < 16; n++) {
            O[n][0] *= alpha0; O[n][1] *= alpha0;
            O[n][2] *= alpha1; O[n][3] *= alpha1;
        }
        #pragma unroll
        for (int kt2 = 0; kt2 < 4; kt2++) {
            #pragma unroll
            for (int nt2 = 0; nt2 < 16; nt2++) {
                uint32_t vbo = (bo - sb) + VB_H + (nt2 * 8 + lr) * 144 + kt2 * 32 + 4 * q;
                uint32_t bhf[2], blf[2];
                bhf[0] = *(const uint32_t*)(sm + vbo);
                bhf[1] = *(const uint32_t*)(sm + vbo + 16);
                blf[0] = *(const uint32_t*)(sm + vbo + (VB_L - VB_H));
                blf[1] = *(const uint32_t*)(sm + vbo + (VB_L - VB_H) + 16);
                mma16816(O[nt2], aPh[kt2], bhf);
                mma16816(O[nt2], aPh[kt2], blf);
                mma16816(O[nt2], aPl[kt2], bhf);
            }
        }

        if (blk + 1 < nblk) {
            CP_WAIT0();
            __syncthreads();
        }
    }

    const float inv0 = 1.0f / lw0;
    const float inv1 = 1.0f / lw1;
    const int m0 = b * T_ + rbase + lr;
    const int m1 = m0 + 8;
    #pragma unroll
    for (int nt2 = 0; nt2 < 16; nt2++) {
        int col = h * D_ + nt2 * 8 + 2 * q;
        float o0 = O[nt2][0] * inv0, o1 = O[nt2][1] * inv0;
        float o2 = O[nt2][2] * inv1, o3 = O[nt2][3] * inv1;
        __nv_bfloat16 h0 = __float2bfloat16(o0), h1 = __float2bfloat16(o1);
        __nv_bfloat16 h2 = __float2bfloat16(o2), h3 = __float2bfloat16(o3);
        __nv_bfloat16 l0 = __float2bfloat16(o0 - __bfloat162float(h0));
        __nv_bfloat16 l1 = __float2bfloat16(o1 - __bfloat162float(h1));
        __nv_bfloat16 l2 = __float2bfloat16(o2 - __bfloat162float(h2));
        __nv_bfloat16 l3 = __float2bfloat16(o3 - __bfloat162float(h3));
        *(__nv_bfloat162*)(outh + (size_t)m0 * C_ + col) = __nv_bfloat162{h0, h1};
        *(__nv_bfloat162*)(outl + (size_t)m0 * C_ + col) = __nv_bfloat162{l0, l1};
        *(__nv_bfloat162*)(outh + (size_t)m1 * C_ + col) = __nv_bfloat162{h2, h3};
        *(__nv_bfloat162*)(outl + (size_t)m1 * C_ + col) = __nv_bfloat162{l2, l3};
    }
}

// ---------------------------------------------------------------------------
extern "C" void kernel_launch(void* const* d_in, const int* in_sizes, int n_in,
                              void* d_out, int out_size)
{
    const float* x     = (const float*)d_in[0];
    const float* W_qkv = (const float*)d_in[1];
    const float* W_out = (const float*)d_in[2];
    float* out = (float*)d_out;

    cudaFuncSetAttribute(attn_hmma,
                         cudaFuncAttributeMaxDynamicSharedMemorySize, SMEM_ATTN);
    cudaFuncSetAttribute(hmma_gemm<1>,
                         cudaFuncAttributeMaxDynamicSharedMemorySize, SMEM_GEMM);
    cudaFuncSetAttribute(hmma_gemm<0>,
                         cudaFuncAttributeMaxDynamicSharedMemorySize, SMEM_GEMM);

    __nv_bfloat16 *hiA, *loA, *hiB1, *loB1, *hiB2, *loB2;
    cudaGetSymbolAddress((void**)&hiA,  g_hiA);
    cudaGetSymbolAddress((void**)&loA,  g_loA);
    cudaGetSymbolAddress((void**)&hiB1, g_hiB1);
    cudaGetSymbolAddress((void**)&loB1, g_loB1);
    cudaGetSymbolAddress((void**)&hiB2, g_hiB2);
    cudaGetSymbolAddress((void**)&loB2, g_loB2);

    const int n4 = (M_ * C_) / 4;

    // 1) split x -> hi/lo bf16 (A operand of QKV GEMM)
    split_kernel<<<(n4 + 255) / 256, 256>>>(x, hiA, loA, n4);
    // 2) transpose+split weights
    tsplit_kernel<<<dim3(N_QKV / 32, C_ / 32), dim3(32, 8)>>>(W_qkv, hiB1, loB1, N_QKV);
    tsplit_kernel<<<dim3(C_ / 32, C_ / 32), dim3(32, 8)>>>(W_out, hiB2, loB2, C_);
    // 3) QKV projection + RoPE -> bf16 hi/lo q/k (and transposed v)
    hmma_gemm<1><<<dim3(N_QKV / 128, M_ / 128), 256, SMEM_GEMM>>>(
        hiA, loA, hiB1, loB1, nullptr, N_QKV);
    // 4) HMMA flash attention -> g_hiA/g_loA (A operand of out-proj)
    attn_hmma<<<dim3(T_ / 128, B_ * H_), 256, SMEM_ATTN>>>(hiA, loA);
    // 5) output projection -> d_out
    hmma_gemm<0><<<dim3(C_ / 128, M_ / 128), 256, SMEM_GEMM>>>(
        hiA, loA, hiB2, loB2, out, C_);
}

// round 11
// speedup vs baseline: 4.4419x; 1.4994x over previous
#include <cuda_runtime.h>
#include <cuda_bf16.h>
#include <cuda_fp16.h>
#include <math.h>
#include <stdint.h>

#define B_  2
#define T_  2048
#define C_  2048
#define H_  16
#define D_  128
#define M_  (B_*T_)      // 4096
#define N_QKV (3*C_)     // 6144

// ---------------------------------------------------------------------------
// Device scratch (allocation-free per harness rules)
// ---------------------------------------------------------------------------
__device__ __nv_bfloat16 g_qh[(size_t)B_*H_*T_*D_];
__device__ __nv_bfloat16 g_ql[(size_t)B_*H_*T_*D_];
__device__ __nv_bfloat16 g_kh[(size_t)B_*H_*T_*D_];
__device__ __nv_bfloat16 g_kl[(size_t)B_*H_*T_*D_];
__device__ __nv_bfloat16 g_vth[(size_t)B_*H_*D_*T_];   // transposed [B,H,D,T]
__device__ __nv_bfloat16 g_vtl[(size_t)B_*H_*D_*T_];

__device__ __half g_hA[(size_t)M_*C_];     // GEMM A operand, fp16 hi
__device__ __half g_lA[(size_t)M_*C_];     // GEMM A operand, fp16 lo
__device__ __half g_B1[(size_t)N_QKV*C_];  // W_qkv^T, single fp16
__device__ __half g_B2[(size_t)C_*C_];     // W_out^T, single fp16

// ---------------------------------------------------------------------------
// PTX helpers
// ---------------------------------------------------------------------------
__device__ __forceinline__ void mma16816bf(float* c, const uint32_t* a, const uint32_t* b) {
    asm volatile(
        "mma.sync.aligned.m16n8k16.row.col.f32.bf16.bf16.f32 "
        "{%0,%1,%2,%3}, {%4,%5,%6,%7}, {%8,%9}, {%0,%1,%2,%3};"
        : "+f"(c[0]), "+f"(c[1]), "+f"(c[2]), "+f"(c[3])
        : "r"(a[0]), "r"(a[1]), "r"(a[2]), "r"(a[3]), "r"(b[0]), "r"(b[1]));
}

__device__ __forceinline__ void mma16816h(float* c, const uint32_t* a, const uint32_t* b) {
    asm volatile(
        "mma.sync.aligned.m16n8k16.row.col.f32.f16.f16.f32 "
        "{%0,%1,%2,%3}, {%4,%5,%6,%7}, {%8,%9}, {%0,%1,%2,%3};"
        : "+f"(c[0]), "+f"(c[1]), "+f"(c[2]), "+f"(c[3])
        : "r"(a[0]), "r"(a[1]), "r"(a[2]), "r"(a[3]), "r"(b[0]), "r"(b[1]));
}

__device__ __forceinline__ void ldsm4(uint32_t* r, uint32_t addr) {
    asm volatile("ldmatrix.sync.aligned.m8n8.x4.shared.b16 {%0,%1,%2,%3}, [%4];"
        : "=r"(r[0]), "=r"(r[1]), "=r"(r[2]), "=r"(r[3]) : "r"(addr));
}

__device__ __forceinline__ uint32_t smem_to_u32(const void* p) {
    uint32_t a;
    asm("{ .reg .u64 t; cvta.to.shared.u64 t, %1; cvt.u32.u64 %0, t; }" : "=r"(a) : "l"(p));
    return a;
}

__device__ __forceinline__ void cp16(uint32_t dst, const void* src) {
    asm volatile("cp.async.cg.shared.global [%0], [%1], 16;" :: "r"(dst), "l"(src));
}
#define CP_COMMIT() asm volatile("cp.async.commit_group;" ::: "memory")
#define CP_WAIT0()  asm volatile("cp.async.wait_group 0;" ::: "memory")
#define CP_WAIT1()  asm volatile("cp.async.wait_group 1;" ::: "memory")

// pack two fp32 -> bf16x2 (lo = first arg -> lower half)
__device__ __forceinline__ uint32_t packbf(float lo, float hi) {
    uint32_t r;
    asm("cvt.rn.bf16x2.f32 %0, %1, %2;" : "=r"(r) : "f"(hi), "f"(lo));
    return r;
}

// ---------------------------------------------------------------------------
// fp32 -> fp16 (hi, lo) split;  fp32 -> fp16 single transpose
// ---------------------------------------------------------------------------
__global__ void split_kernel(const float* __restrict__ src,
                             __half* __restrict__ hi,
                             __half* __restrict__ lo, int n4)
{
    int i = blockIdx.x * blockDim.x + threadIdx.x;
    if (i >= n4) return;
    float4 v = ((const float4*)src)[i];
    __half h0 = __float2half(v.x);
    __half h1 = __float2half(v.y);
    __half h2 = __float2half(v.z);
    __half h3 = __float2half(v.w);
    __half l0 = __float2half(v.x - __half2float(h0));
    __half l1 = __float2half(v.y - __half2float(h1));
    __half l2 = __float2half(v.z - __half2float(h2));
    __half l3 = __float2half(v.w - __half2float(h3));
    __half2* hp = (__half2*)hi;
    __half2* lp = (__half2*)lo;
    hp[i*2]   = __half2{h0, h1};
    hp[i*2+1] = __half2{h2, h3};
    lp[i*2]   = __half2{l0, l1};
    lp[i*2+1] = __half2{l2, l3};
}

// Transpose + convert: W [K=2048, N] -> fp16 [N, 2048]
__global__ void tsplit1_kernel(const float* __restrict__ W,
                               __half* __restrict__ hi, int N)
{
    __shared__ float t[32][33];
    int n0 = blockIdx.x * 32, k0 = blockIdx.y * 32;
    int tx = threadIdx.x, ty = threadIdx.y;
    #pragma unroll
    for (int i = 0; i < 4; i++)
        t[ty + i*8][tx] = W[(size_t)(k0 + ty + i*8) * N + n0 + tx];
    __syncthreads();
    #pragma unroll
    for (int i = 0; i < 4; i++) {
        int r = ty + i*8;
        hi[(size_t)(n0 + r) * 2048 + k0 + tx] = __float2half(t[tx][r]);
    }
}

// ---------------------------------------------------------------------------
// HMMA fp16 2-term GEMM: C = (Ah+Al) * B^T.  cp.async 3-stage pipeline,
// ldmatrix fragments, CTA 128x128, 8 warps (4m x 2n), K-chunk 32, 2 CTAs/SM.
// EPI=1: RoPE + bf16 hi/lo scatter (Q,K normal; V transposed).
// EPI=0: plain fp32 store.
// ---------------------------------------------------------------------------
#define ASTR 40                          // padded fp16 row stride
#define TILE_ELEMS (128 * ASTR)          // 5120 elems per matrix tile
#define TILE_B     (TILE_ELEMS * 2)      // 10240 bytes
#define STAGE_B    (3 * TILE_B)          // 30720 bytes per stage (Ah, Al, B)
#define NSTAGE     3
#define SMEM_GEMM  (NSTAGE * STAGE_B)    // 92160 bytes -> 2 CTAs/SM
#define NCH        64                    // 2048 / 32

template<int EPI>
__global__ void __launch_bounds__(256, 2) hmma_gemm(
    const __half* __restrict__ hiA, const __half* __restrict__ loA,
    const __half* __restrict__ Bw,
    float* __restrict__ Cout, int Ntot)
{
    extern __shared__ char smraw[];
    const uint32_t sb = smem_to_u32(smraw);

    const int tid = threadIdx.x;
    const int lane = tid & 31;
    const int wid = tid >> 5;
    const int warp_m = wid & 3;
    const int warp_n = wid >> 2;
    const int bn = blockIdx.x * 128;
    const int bm = blockIdx.y * 128;

    float acc[2][8][4];
    #pragma unroll
    for (int mt = 0; mt < 2; mt++)
        #pragma unroll
        for (int nt = 0; nt < 8; nt++)
            #pragma unroll
            for (int e = 0; e < 4; e++) acc[mt][nt][e] = 0.0f;

    // stage loader: 3 tiles x 128 rows x 32 halves (4 x 16B per row)
    const int lrow = tid >> 2;                  // 0..63
    const int lc   = (tid & 3) * 8;             // elem offset {0,8,16,24}
    auto load_stage = [&](int st, int k0) {
        uint32_t bo = sb + st * STAGE_B;
        #pragma unroll
        for (int i = 0; i < 2; i++) {
            int row = lrow + i * 64;
            uint32_t so = (uint32_t)(row * ASTR + lc) * 2;
            size_t ga = (size_t)(bm + row) * 2048 + k0 + lc;
            size_t gb = (size_t)(bn + row) * 2048 + k0 + lc;
            cp16(bo + 0*TILE_B + so, hiA + ga);
            cp16(bo + 1*TILE_B + so, loA + ga);
            cp16(bo + 2*TILE_B + so, Bw + gb);
        }
    };

    // ldmatrix address components
    const int a_row = warp_m * 32 + (lane & 7) + ((lane >> 3) & 1) * 8;
    const int a_k8  = (lane >> 4) * 8;
    const int b_row = warp_n * 64 + (lane & 7) + (lane >> 4) * 8;
    const int b_k8  = ((lane >> 3) & 1) * 8;

    auto compute_stage = [&](int st) {
        uint32_t bo = sb + st * STAGE_B;
        #pragma unroll
        for (int ks = 0; ks < 32; ks += 16) {
            uint32_t ah[2][4], al[2][4], bh[4][4];
            #pragma unroll
            for (int mt = 0; mt < 2; mt++) {
                uint32_t ao = (uint32_t)((a_row + mt * 16) * ASTR + ks + a_k8) * 2;
                ldsm4(ah[mt], bo + 0*TILE_B + ao);
                ldsm4(al[mt], bo + 1*TILE_B + ao);
            }
            #pragma unroll
            for (int p = 0; p < 4; p++) {
                uint32_t bo2 = (uint32_t)((b_row + p * 16) * ASTR + ks + b_k8) * 2;
                ldsm4(bh[p], bo + 2*TILE_B + bo2);
            }
            #pragma unroll
            for (int mt = 0; mt < 2; mt++)
                #pragma unroll
                for (int p = 0; p < 4; p++) {
                    mma16816h(acc[mt][2*p+0], ah[mt], &bh[p][0]);
                    mma16816h(acc[mt][2*p+0], al[mt], &bh[p][0]);
                    mma16816h(acc[mt][2*p+1], ah[mt], &bh[p][2]);
                    mma16816h(acc[mt][2*p+1], al[mt], &bh[p][2]);
                }
        }
    };

    // prime pipeline: stages 0, 1
    load_stage(0, 0);
    CP_COMMIT();
    load_stage(1, 32);
    CP_COMMIT();

    for (int c = 0; c < NCH; c++) {
        CP_WAIT1();
        __syncthreads();
        compute_stage(c % NSTAGE);
        if (c + 2 < NCH)
            load_stage((c + 2) % NSTAGE, (c + 2) * 32);
        CP_COMMIT();
    }

    // ---- Epilogue ----
    const int lr = lane >> 2;
    const int lk = (lane & 3) * 2;

    if (EPI == 1) {
        const int sub = bn >> 11;              // 0=q, 1=k, 2=v
        const int h   = (bn >> 7) & (H_ - 1);
        const float ROPE_K = 9.210340371976184f / (float)D_;
        float invf[8];
        #pragma unroll
        for (int nt = 0; nt < 8; nt++)
            invf[nt] = expf(-(float)(warp_n * 64 + nt * 8 + lk) * ROPE_K);
        #pragma unroll
        for (int mt = 0; mt < 2; mt++) {
            #pragma unroll
            for (int half = 0; half < 2; half++) {
                int m = bm + warp_m * 32 + mt * 16 + lr + half * 8;
                int bidx = m >> 11;
                int t    = m & (T_ - 1);
                size_t rowoff = ((size_t)(bidx * H_ + h) * T_ + t) * D_;
                #pragma unroll
                for (int nt = 0; nt < 8; nt++) {
                    int d = warp_n * 64 + nt * 8 + lk;
                    float v0 = acc[mt][nt][half * 2 + 0];
                    float v1 = acc[mt][nt][half * 2 + 1];
                    if (sub < 2) {
                        float sn, cs;
                        sincosf((float)t * invf[nt], &sn, &cs);
                        float o0 = v0 * cs - v1 * sn;
                        float o1 = v1 * cs + v0 * sn;
                        v0 = o0; v1 = o1;
                    }
                    __nv_bfloat16 h0 = __float2bfloat16(v0);
                    __nv_bfloat16 h1 = __float2bfloat16(v1);
                    __nv_bfloat16 l0 = __float2bfloat16(v0 - __bfloat162float(h0));
                    __nv_bfloat16 l1 = __float2bfloat16(v1 - __bfloat162float(h1));
                    if (sub < 2) {
                        __nv_bfloat16* dh = (sub == 0) ? g_qh : g_kh;
                        __nv_bfloat16* dl = (sub == 0) ? g_ql : g_kl;
                        *(__nv_bfloat162*)(dh + rowoff + d) = __nv_bfloat162{h0, h1};
                        *(__nv_bfloat162*)(dl + rowoff + d) = __nv_bfloat162{l0, l1};
                    } else {
                        size_t vb = ((size_t)(bidx * H_ + h) * D_ + d) * T_ + t;
                        g_vth[vb]      = h0;
                        g_vth[vb + T_] = h1;
                        g_vtl[vb]      = l0;
                        g_vtl[vb + T_] = l1;
                    }
                }
            }
        }
    } else {
        #pragma unroll
        for (int mt = 0; mt < 2; mt++) {
            #pragma unroll
            for (int half = 0; half < 2; half++) {
                int m = bm + warp_m * 32 + mt * 16 + lr + half * 8;
                float* dst = Cout + (size_t)m * Ntot + bn + warp_n * 64 + lk;
                #pragma unroll
                for (int nt = 0; nt < 8; nt++)
                    *(float2*)(dst + nt * 8) =
                        make_float2(acc[mt][nt][half * 2 + 0], acc[mt][nt][half * 2 + 1]);
            }
        }
    }
}

// ---------------------------------------------------------------------------
// HMMA flash attention (bf16 3-term; unchanged math). Epilogue now emits
// fp16 hi/lo into the out-proj A operand.
// ---------------------------------------------------------------------------
#define SQ_H   0
#define SQ_L   34816
#define SBUF0  69632
#define KB_H   0
#define KB_L   17408
#define VB_H   34816
#define VB_L   53248
#define ABUF_SZ 71680
#define SMEM_ATTN (SBUF0 + 2 * ABUF_SZ)   // 212992 bytes

__global__ void __launch_bounds__(256, 1) attn_hmma(
    __half* __restrict__ outh, __half* __restrict__ outl)
{
    extern __shared__ char sm[];
    const uint32_t sb = smem_to_u32(sm);

    const int tid  = threadIdx.x;
    const int lane = tid & 31;
    const int w    = tid >> 5;
    const int lr   = lane >> 2;
    const int q    = lane & 3;
    const int qt   = 15 - blockIdx.x;          // longest tiles first
    const int bh   = blockIdx.y;
    const int b    = bh >> 4;
    const int h    = bh & (H_ - 1);

    const size_t bhT = (size_t)bh * T_;

    {
        const __nv_bfloat16* qh = g_qh + (bhT + qt * 128) * D_;
        const __nv_bfloat16* ql = g_ql + (bhT + qt * 128) * D_;
        #pragma unroll
        for (int i = 0; i < 8; i++) {
            int idx = tid + i * 256;
            int row = idx >> 4, c = idx & 15;
            cp16(sb + SQ_H + row * 272 + c * 16, qh + row * D_ + c * 8);
            cp16(sb + SQ_L + row * 272 + c * 16, ql + row * D_ + c * 8);
        }
    }

    auto loadKV = [&](int blk, int buf) {
        uint32_t bo = sb + SBUF0 + buf * ABUF_SZ;
        const __nv_bfloat16* kh = g_kh + (bhT + blk * 64) * D_;
        const __nv_bfloat16* kl = g_kl + (bhT + blk * 64) * D_;
        const __nv_bfloat16* vh = g_vth + (size_t)bh * D_ * T_ + blk * 64;
        const __nv_bfloat16* vl = g_vtl + (size_t)bh * D_ * T_ + blk * 64;
        #pragma unroll
        for (int i = 0; i < 4; i++) {
            int idx = tid + i * 256;
            int row = idx >> 4, c = idx & 15;
            cp16(bo + KB_H + row * 272 + c * 16, kh + row * D_ + c * 8);
            cp16(bo + KB_L + row * 272 + c * 16, kl + row * D_ + c * 8);
            int vr = idx >> 3, vc = idx & 7;
            cp16(bo + VB_H + vr * 144 + vc * 16, vh + (size_t)vr * T_ + vc * 8);
            cp16(bo + VB_L + vr * 144 + vc * 16, vl + (size_t)vr * T_ + vc * 8);
        }
    };

    loadKV(0, 0);
    CP_COMMIT();
    CP_WAIT0();
    __syncthreads();

    const int nblk = 2 * qt + 2;
    const float scale = 0.08838834764831845f;

    float mr0 = -INFINITY, mr1 = -INFINITY, lw0 = 0.0f, lw1 = 0.0f;
    float O[16][4];
    #pragma unroll
    for (int n = 0; n < 16; n++)
        #pragma unroll
        for (int e = 0; e < 4; e++) O[n][e] = 0.0f;

    const int rbase = qt * 128 + 16 * w;

    for (int blk = 0; blk < nblk; blk++) {
        const uint32_t bo = sb + SBUF0 + (blk & 1) * ABUF_SZ;
        if (blk + 1 < nblk) {
            loadKV(blk + 1, (blk & 1) ^ 1);
            CP_COMMIT();
        }

        float s[8][4];
        #pragma unroll
        for (int n = 0; n < 8; n++)
            #pragma unroll
            for (int e = 0; e < 4; e++) s[n][e] = 0.0f;

        #pragma unroll
        for (int kt = 0; kt < 8; kt++) {
            uint32_t ah[4], al[4];
            uint32_t ab = sb + SQ_H + (16 * w + lr) * 272 + kt * 32 + 4 * q;
            ah[0] = *(const uint32_t*)(sm + (ab - sb));
            ah[1] = *(const uint32_t*)(sm + (ab - sb) + 8 * 272);
            ah[2] = *(const uint32_t*)(sm + (ab - sb) + 16);
            ah[3] = *(const uint32_t*)(sm + (ab - sb) + 8 * 272 + 16);
            uint32_t lb = (ab - sb) + (SQ_L - SQ_H);
            al[0] = *(const uint32_t*)(sm + lb);
            al[1] = *(const uint32_t*)(sm + lb + 8 * 272);
            al[2] = *(const uint32_t*)(sm + lb + 16);
            al[3] = *(const uint32_t*)(sm + lb + 8 * 272 + 16);
            #pragma unroll
            for (int nt = 0; nt < 8; nt++) {
                uint32_t bbo = (bo - sb) + KB_H + (nt * 8 + lr) * 272 + kt * 32 + 4 * q;
                uint32_t bhf[2], blf[2];
                bhf[0] = *(const uint32_t*)(sm + bbo);
                bhf[1] = *(const uint32_t*)(sm + bbo + 16);
                blf[0] = *(const uint32_t*)(sm + bbo + (KB_L - KB_H));
                blf[1] = *(const uint32_t*)(sm + bbo + (KB_L - KB_H) + 16);
                mma16816bf(s[nt], ah, bhf);
                mma16816bf(s[nt], ah, blf);
                mma16816bf(s[nt], al, bhf);
            }
        }

        const bool need_mask = (blk * 64 + 63) > rbase;
        #pragma unroll
        for (int nt = 0; nt < 8; nt++) {
            #pragma unroll
            for (int e = 0; e < 4; e++) {
                float v = s[nt][e] * scale;
                if (need_mask) {
                    int ckey = blk * 64 + nt * 8 + 2 * q + (e & 1);
                    int r = rbase + lr + ((e >> 1) ? 8 : 0);
                    if (ckey > r) v = -1e30f;
                }
                s[nt][e] = v;
            }
        }

        float mx0 = -1e30f, mx1 = -1e30f;
        #pragma unroll
        for (int nt = 0; nt < 8; nt++) {
            mx0 = fmaxf(mx0, fmaxf(s[nt][0], s[nt][1]));
            mx1 = fmaxf(mx1, fmaxf(s[nt][2], s[nt][3]));
        }
        mx0 = fmaxf(mx0, __shfl_xor_sync(0xffffffff, mx0, 1));
        mx0 = fmaxf(mx0, __shfl_xor_sync(0xffffffff, mx0, 2));
        mx1 = fmaxf(mx1, __shfl_xor_sync(0xffffffff, mx1, 1));
        mx1 = fmaxf(mx1, __shfl_xor_sync(0xffffffff, mx1, 2));
        float mn0 = fmaxf(mr0, mx0);
        float mn1 = fmaxf(mr1, mx1);
        float alpha0 = __expf(mr0 - mn0);
        float alpha1 = __expf(mr1 - mn1);

        float sum0 = 0.0f, sum1 = 0.0f;
        uint32_t aPh[4][4], aPl[4][4];
        #pragma unroll
        for (int nt = 0; nt < 8; nt++) {
            float p0 = __expf(s[nt][0] - mn0);
            float p1 = __expf(s[nt][1] - mn0);
            float p2 = __expf(s[nt][2] - mn1);
            float p3 = __expf(s[nt][3] - mn1);
            sum0 += p0 + p1;
            sum1 += p2 + p3;
            float h0 = __bfloat162float(__float2bfloat16(p0));
            float h1 = __bfloat162float(__float2bfloat16(p1));
            float h2 = __bfloat162float(__float2bfloat16(p2));
            float h3 = __bfloat162float(__float2bfloat16(p3));
            int kt2 = nt >> 1;
            int hi2 = (nt & 1) << 1;
            aPh[kt2][hi2 + 0] = packbf(h0, h1);
            aPh[kt2][hi2 + 1] = packbf(h2, h3);
            aPl[kt2][hi2 + 0] = packbf(p0 - h0, p1 - h1);
            aPl[kt2][hi2 + 1] = packbf(p2 - h2, p3 - h3);
        }
        sum0 += __shfl_xor_sync(0xffffffff, sum0, 1);
        sum0 += __shfl_xor_sync(0xffffffff, sum0, 2);
        sum1 += __shfl_xor_sync(0xffffffff, sum1, 1);
        sum1 += __shfl_xor_sync(0xffffffff, sum1, 2);
        lw0 = lw0 * alpha0 + sum0;
        lw1 = lw1 * alpha1 + sum1;
        mr0 = mn0;
        mr1 = mn1;

        #pragma unroll
        for (int n = 0; n < 16; n++) {
            O[n][0] *= alpha0; O[n][1] *= alpha0;
            O[n][2] *= alpha1; O[n][3] *= alpha1;
        }
        #pragma unroll
        for (int kt2 = 0; kt2 < 4; kt2++) {
            #pragma unroll
            for (int nt2 = 0; nt2 < 16; nt2++) {
                uint32_t vbo = (bo - sb) + VB_H + (nt2 * 8 + lr) * 144 + kt2 * 32 + 4 * q;
                uint32_t bhf[2], blf[2];
                bhf[0] = *(const uint32_t*)(sm + vbo);
                bhf[1] = *(const uint32_t*)(sm + vbo + 16);
                blf[0] = *(const uint32_t*)(sm + vbo + (VB_L - VB_H));
                blf[1] = *(const uint32_t*)(sm + vbo + (VB_L - VB_H) + 16);
                mma16816bf(O[nt2], aPh[kt2], bhf);
                mma16816bf(O[nt2], aPh[kt2], blf);
                mma16816bf(O[nt2], aPl[kt2], bhf);
            }
        }

        if (blk + 1 < nblk) {
            CP_WAIT0();
            __syncthreads();
        }
    }

    // ---- epilogue: normalize, split to fp16 hi/lo for the out-proj ----
    const float inv0 = 1.0f / lw0;
    const float inv1 = 1.0f / lw1;
    const int m0 = b * T_ + rbase + lr;
    const int m1 = m0 + 8;
    #pragma unroll
    for (int nt2 = 0; nt2 < 16; nt2++) {
        int col = h * D_ + nt2 * 8 + 2 * q;
        float o0 = O[nt2][0] * inv0, o1 = O[nt2][1] * inv0;
        float o2 = O[nt2][2] * inv1, o3 = O[nt2][3] * inv1;
        __half h0 = __float2half(o0), h1 = __float2half(o1);
        __half h2 = __float2half(o2), h3 = __float2half(o3);
        __half l0 = __float2half(o0 - __half2float(h0));
        __half l1 = __float2half(o1 - __half2float(h1));
        __half l2 = __float2half(o2 - __half2float(h2));
        __half l3 = __float2half(o3 - __half2float(h3));
        *(__half2*)(outh + (size_t)m0 * C_ + col) = __half2{h0, h1};
        *(__half2*)(outl + (size_t)m0 * C_ + col) = __half2{l0, l1};
        *(__half2*)(outh + (size_t)m1 * C_ + col) = __half2{h2, h3};
        *(__half2*)(outl + (size_t)m1 * C_ + col) = __half2{l2, l3};
    }
}

// ---------------------------------------------------------------------------
extern "C" void kernel_launch(void* const* d_in, const int* in_sizes, int n_in,
                              void* d_out, int out_size)
{
    const float* x     = (const float*)d_in[0];
    const float* W_qkv = (const float*)d_in[1];
    const float* W_out = (const float*)d_in[2];
    float* out = (float*)d_out;

    cudaFuncSetAttribute(attn_hmma,
                         cudaFuncAttributeMaxDynamicSharedMemorySize, SMEM_ATTN);
    cudaFuncSetAttribute(hmma_gemm<1>,
                         cudaFuncAttributeMaxDynamicSharedMemorySize, SMEM_GEMM);
    cudaFuncSetAttribute(hmma_gemm<0>,
                         cudaFuncAttributeMaxDynamicSharedMemorySize, SMEM_GEMM);

    __half *hA, *lA, *B1, *B2;
    cudaGetSymbolAddress((void**)&hA, g_hA);
    cudaGetSymbolAddress((void**)&lA, g_lA);
    cudaGetSymbolAddress((void**)&B1, g_B1);
    cudaGetSymbolAddress((void**)&B2, g_B2);

    const int n4 = (M_ * C_) / 4;

    // 1) split x -> fp16 hi/lo (A operand of QKV GEMM)
    split_kernel<<<(n4 + 255) / 256, 256>>>(x, hA, lA, n4);
    // 2) transpose+convert weights to single fp16
    tsplit1_kernel<<<dim3(N_QKV / 32, C_ / 32), dim3(32, 8)>>>(W_qkv, B1, N_QKV);
    tsplit1_kernel<<<dim3(C_ / 32, C_ / 32), dim3(32, 8)>>>(W_out, B2, C_);
    // 3) QKV projection + RoPE -> bf16 hi/lo q/k (and transposed v)
    hmma_gemm<1><<<dim3(N_QKV / 128, M_ / 128), 256, SMEM_GEMM>>>(
        hA, lA, B1, nullptr, N_QKV);
    // 4) HMMA flash attention -> fp16 hi/lo (A operand of out-proj)
    attn_hmma<<<dim3(T_ / 128, B_ * H_), 256, SMEM_ATTN>>>(hA, lA);
    // 5) output projection -> d_out
    hmma_gemm<0><<<dim3(C_ / 128, M_ / 128), 256, SMEM_GEMM>>>(
        hA, lA, B2, out, C_);
}